// round 14
// baseline (speedup 1.0000x reference)
#include <cuda_runtime.h>
#include <cuda_bf16.h>
#include <math.h>
#include <stdint.h>

#define BATCH 2
#define SEQ   2048
#define DMODEL 1024
#define NHEAD 16
#define HDIM  64
#define MROWS (BATCH*SEQ)          // 4096
#define NBH   (BATCH*NHEAD)        // 32
#define NROOT 240
#define NTILE 32                   // key tiles of 64

// Scratch (device globals; no allocation allowed)
__device__ float g_k[MROWS*DMODEL];
__device__ float g_v[MROWS*DMODEL];
__device__ float g_o[MROWS*DMODEL];
__device__ float g_xr[MROWS*DMODEL];        // tf32-rounded x
__device__ float g_wkr[DMODEL*DMODEL];      // tf32-rounded W^T (n-major)
__device__ float g_wvr[DMODEL*DMODEL];
__device__ float g_wor[DMODEL*DMODEL];
__device__ float g_E[NBH*NROOT*SEQ];
__device__ float g_P[NBH*NTILE*NROOT*64];   // CUMULATIVE per-tile PV partials
__device__ float g_lp[NBH*NROOT*NTILE];     // CUMULATIVE per-tile E-row sums
__device__ float g_coords[MROWS*128];
__device__ float g_coords2[MROWS*128];
__device__ int   g_idx[NBH*SEQ];
__device__ float g_Wqe8[DMODEL*128];
__device__ float g_RW[NROOT*HDIM];

// ===========================================================================
// helpers
// ===========================================================================
__device__ __forceinline__ uint32_t smem_u32(const void* p) {
    uint32_t a;
    asm("{ .reg .u64 t; cvta.to.shared.u64 t, %1; cvt.u32.u64 %0, t; }"
        : "=r"(a) : "l"(p));
    return a;
}
#define CP16(dst, src) \
    asm volatile("cp.async.cg.shared.global [%0], [%1], 16;" :: "r"(dst), "l"(src) : "memory")
#define CP_COMMIT() asm volatile("cp.async.commit_group;" ::: "memory")
#define CP_WAIT(n)  asm volatile("cp.async.wait_group %0;" :: "n"(n) : "memory")

__device__ __forceinline__ void cvt3(float x, uint32_t& hi, uint32_t& lo) {
    asm("cvt.rna.tf32.f32 %0, %1;" : "=r"(hi) : "f"(x));
    float r = x - __uint_as_float(hi);
    asm("cvt.rna.tf32.f32 %0, %1;" : "=r"(lo) : "f"(r));
}
__device__ __forceinline__ uint32_t cvt1(float x) {
    uint32_t t;
    asm("cvt.rna.tf32.f32 %0, %1;" : "=r"(t) : "f"(x));
    return t;
}
__device__ __forceinline__ float rtf32(float x) { return __uint_as_float(cvt1(x)); }

#define MMA8(c, a, b) \
    asm volatile("mma.sync.aligned.m16n8k8.row.col.f32.tf32.tf32.f32 " \
        "{%0,%1,%2,%3}, {%4,%5,%6,%7}, {%8,%9}, {%0,%1,%2,%3};" \
        : "+f"((c)[0]), "+f"((c)[1]), "+f"((c)[2]), "+f"((c)[3]) \
        : "r"((a)[0]), "r"((a)[1]), "r"((a)[2]), "r"((a)[3]), \
          "r"((b)[0]), "r"((b)[1]))

#define LDSM4(r0, r1, r2, r3, addr) \
    asm volatile("ldmatrix.sync.aligned.m8n8.x4.shared.b16 {%0,%1,%2,%3}, [%4];" \
        : "=r"(r0), "=r"(r1), "=r"(r2), "=r"(r3) : "r"(addr))

// ===========================================================================
// fused prep: round x, transpose+round Wk/Wv/Wout -> [n][k], Wqe8, RW tables
// ===========================================================================
#define PB_X (MROWS * DMODEL / 256)      // 16384
#define PB_WT ((DMODEL / 32) * (DMODEL / 32))  // 1024 tiles per weight
#define PB_Q 512
#define PB_T 8
#define PREP_BLKS (PB_X + 3 * PB_WT + PB_Q + PB_T)

__global__ __launch_bounds__(256) void prep(const float* __restrict__ x,
                                            const float* __restrict__ Wq,
                                            const float* __restrict__ Wk,
                                            const float* __restrict__ Wv,
                                            const float* __restrict__ Wo,
                                            const float* __restrict__ Wt,
                                            const float* __restrict__ Wf) {
    int tid = threadIdx.x;
    int blk = blockIdx.x;
    if (blk < PB_X) {
        int i = blk * 256 + tid;
        g_xr[i] = rtf32(x[i]);
        return;
    }
    blk -= PB_X;
    if (blk < 3 * PB_WT) {
        // 32x32 tile transpose + round: d[n][k] = rtf32(s[k][n])
        __shared__ float ts[32][33];
        int sel = blk / PB_WT;
        int t = blk % PB_WT;
        const float* s = (sel == 0) ? Wk : (sel == 1) ? Wv : Wo;
        float* d = (sel == 0) ? g_wkr : (sel == 1) ? g_wvr : g_wor;
        int n0 = (t & 31) * 32, k0 = (t >> 5) * 32;
        int cc = tid & 31, rr = tid >> 5;          // rr 0..7
#pragma unroll
        for (int i = 0; i < 4; i++) {
            int r = rr + i * 8;
            ts[r][cc] = s[(size_t)(k0 + r) * DMODEL + n0 + cc];
        }
        __syncthreads();
#pragma unroll
        for (int i = 0; i < 4; i++) {
            int r = rr + i * 8;
            d[(size_t)(n0 + r) * DMODEL + k0 + cc] = rtf32(ts[cc][r]);
        }
        return;
    }
    blk -= 3 * PB_WT;
    if (blk < PB_Q) {
        int i = blk * 256 + tid;           // < 1024*128
        int in = i >> 7, c = i & 127, h = c >> 3, j = c & 7;
        float s = 0.f;
#pragma unroll
        for (int e = 0; e < 64; e++) s += Wq[(size_t)in * DMODEL + h * 64 + e] * Wt[e * 8 + j];
        g_Wqe8[i] = s;
        return;
    }
    blk -= PB_Q;
    {
        __shared__ float roots[NROOT * 8];
        for (int i = tid; i < NROOT * 8; i += 256) {
            int r = i >> 3, d = i & 7;
            float v;
            if (r < 112) {
                int p = r >> 2, s = r & 3;
                int a = 0, b = 1, cnt = 0; bool done = false;
                for (a = 0; a < 8 && !done; a++) {
                    for (b = a + 1; b < 8; b++) {
                        if (cnt == p) { done = true; break; }
                        cnt++;
                    }
                }
                a--;
                float si = (s & 2) ? -1.f : 1.f;
                float sj = (s & 1) ? -1.f : 1.f;
                v = (d == a) ? si : ((d == b) ? sj : 0.f);
            } else {
                int k = r - 112;
                int mask = (k << 1) | (__popc(k) & 1);
                v = ((mask >> d) & 1) ? -0.5f : 0.5f;
            }
            roots[i] = v;
        }
        __syncthreads();
        int base = blk * (NROOT * HDIM / PB_T);
        for (int t = tid; t < NROOT * HDIM / PB_T; t += 256) {
            int i = base + t;
            int r = i >> 6, d = i & 63;
            float s = 0.f;
#pragma unroll
            for (int j = 0; j < 8; j++) s += roots[r * 8 + j] * Wf[j * HDIM + d];
            g_RW[i] = rtf32(0.125f * s);
        }
    }
}

// ===========================================================================
// mma.sync tf32 GEMM.
// SPLIT3=false: B is W^T [N][K] n-major; frags via ldmatrix.x4 (8 LDSM / ks).
// SPLIT3=true : legacy scalar path, B row-major [K][N], 3-product split.
// 128 threads / 4 warps, warp tile 64x64.
// ===========================================================================
#define AS_STRIDE 36
#define BS_STRIDE 132
#define AS_F (128 * AS_STRIDE)          // 4608
#define BS_F (32 * BS_STRIDE)           // legacy B region
// stage sizes (floats)
#define STG_T (AS_F + AS_F)             // ldsm path: A + B^T, both 128x36
#define STG_S (AS_F + BS_F)             // split3 legacy
#define GM_SMEM_T (2 * STG_T * 4)       // 73728
#define GM_SMEM_S (2 * STG_S * 4)       // 70656

extern __shared__ float smf[];

template <bool SPLIT3>
__global__ __launch_bounds__(128, SPLIT3 ? 1 : 2)
void gemm_mma(const float* __restrict__ A,
              const float* __restrict__ B0, float* __restrict__ C0,
              const float* __restrict__ B1, float* __restrict__ C1,
              int N, int K, int lda, int koff) {
    const float* B = blockIdx.z ? B1 : B0;
    float* C = blockIdx.z ? C1 : C0;
    A += (size_t)blockIdx.z * koff;
    int tid = threadIdx.x;
    int lane = tid & 31, w = tid >> 5;
    int lq = lane & 3, lr = lane >> 2;
    int wm = (w & 1) * 64, wn = (w >> 1) * 64;
    int n0 = blockIdx.x * 128, m0 = blockIdx.y * 128;
    uint32_t sb = smem_u32(smf);
    const int STG_F = SPLIT3 ? STG_S : STG_T;

    float acc[4][8][4];
#pragma unroll
    for (int mt = 0; mt < 4; mt++)
#pragma unroll
        for (int nt = 0; nt < 8; nt++)
#pragma unroll
            for (int j = 0; j < 4; j++) acc[mt][nt][j] = 0.f;

    // per-lane LDSM base addresses (ldsm path)
    uint32_t a_base[4], b_base[4];
    if (!SPLIT3) {
        int tile = lane >> 3, rin = lane & 7;
        int trow = (tile & 1) * 8 + rin;
        int tcol = (tile >> 1) * 4;
#pragma unroll
        for (int mt = 0; mt < 4; mt++)
            a_base[mt] = sb + (uint32_t)((wm + mt * 16 + trow) * AS_STRIDE + tcol) * 4;
#pragma unroll
        for (int ntp = 0; ntp < 4; ntp++)
            b_base[ntp] = sb + (uint32_t)(AS_F + (wn + ntp * 16 + trow) * AS_STRIDE + tcol) * 4;
    }

    int ar[8], aq[8], bk[8], bn[8];
#pragma unroll
    for (int i = 0; i < 8; i++) {
        int idx = tid + i * 128;
        ar[i] = idx >> 3; aq[i] = idx & 7;
        bk[i] = idx >> 5; bn[i] = idx & 31;
    }

    auto issue_chunk = [&](int c) {
        int k0 = c * 32;
        uint32_t base = sb + (uint32_t)(c & 1) * (STG_F * 4);
#pragma unroll
        for (int i = 0; i < 8; i++)
            CP16(base + (uint32_t)(ar[i] * AS_STRIDE + aq[i] * 4) * 4,
                 A + (size_t)(m0 + ar[i]) * lda + k0 + aq[i] * 4);
        if (!SPLIT3) {
            // B^T [N][K]: rows are n, k-contiguous — same pattern as A
#pragma unroll
            for (int i = 0; i < 8; i++)
                CP16(base + (uint32_t)(AS_F + ar[i] * AS_STRIDE + aq[i] * 4) * 4,
                     B + (size_t)(n0 + ar[i]) * K + k0 + aq[i] * 4);
        } else {
#pragma unroll
            for (int i = 0; i < 8; i++)
                CP16(base + (uint32_t)(AS_F + bk[i] * BS_STRIDE + bn[i] * 4) * 4,
                     B + (size_t)(k0 + bk[i]) * N + n0 + bn[i] * 4);
        }
        CP_COMMIT();
    };

    issue_chunk(0);
    int nchunk = K >> 5;

    for (int c = 0; c < nchunk; c++) {
        if (c < nchunk - 1) { issue_chunk(c + 1); CP_WAIT(1); }
        else                { CP_WAIT(0); }
        __syncthreads();

        uint32_t stg = (uint32_t)(c & 1) * (STG_F * 4);
        const float* As = smf + (c & 1) * STG_F;
        const float* Bs = As + AS_F;

#pragma unroll
        for (int ks = 0; ks < 4; ks++) {
            int kk = ks * 8;
            if (!SPLIT3) {
                uint32_t Af[4][4];
#pragma unroll
                for (int mt = 0; mt < 4; mt++)
                    LDSM4(Af[mt][0], Af[mt][1], Af[mt][2], Af[mt][3],
                          a_base[mt] + stg + kk * 4);
#pragma unroll
                for (int ntp = 0; ntp < 4; ntp++) {
                    uint32_t r0, r1, r2, r3;
                    LDSM4(r0, r1, r2, r3, b_base[ntp] + stg + kk * 4);
                    uint32_t be[2] = {r0, r2}, bo[2] = {r1, r3};
#pragma unroll
                    for (int mt = 0; mt < 4; mt++) {
                        MMA8(acc[mt][2 * ntp],     Af[mt], be);
                        MMA8(acc[mt][2 * ntp + 1], Af[mt], bo);
                    }
                }
            } else {
                uint32_t Ah[4][4], Al[4][4];
#pragma unroll
                for (int mt = 0; mt < 4; mt++) {
                    int rb = wm + mt * 16 + lr;
                    cvt3(As[rb * AS_STRIDE + kk + lq],           Ah[mt][0], Al[mt][0]);
                    cvt3(As[(rb + 8) * AS_STRIDE + kk + lq],     Ah[mt][1], Al[mt][1]);
                    cvt3(As[rb * AS_STRIDE + kk + lq + 4],       Ah[mt][2], Al[mt][2]);
                    cvt3(As[(rb + 8) * AS_STRIDE + kk + lq + 4], Ah[mt][3], Al[mt][3]);
                }
                uint32_t Bh[8][2], Bl[8][2];
#pragma unroll
                for (int nt = 0; nt < 8; nt++) {
                    int cc = wn + nt * 8 + lr;
                    cvt3(Bs[(kk + lq) * BS_STRIDE + cc],     Bh[nt][0], Bl[nt][0]);
                    cvt3(Bs[(kk + lq + 4) * BS_STRIDE + cc], Bh[nt][1], Bl[nt][1]);
                }
#pragma unroll
                for (int mt = 0; mt < 4; mt++)
#pragma unroll
                    for (int nt = 0; nt < 8; nt++) {
                        MMA8(acc[mt][nt], Ah[mt], Bh[nt]);
                        MMA8(acc[mt][nt], Al[mt], Bh[nt]);
                        MMA8(acc[mt][nt], Ah[mt], Bl[nt]);
                    }
            }
        }
        __syncthreads();
    }

#pragma unroll
    for (int mt = 0; mt < 4; mt++) {
        int row = m0 + wm + mt * 16 + lr;
#pragma unroll
        for (int nt = 0; nt < 8; nt++) {
            int col = n0 + wn + nt * 8 + lq * 2;
            if (SPLIT3) {
                *(float2*)(C + (size_t)row * N + col) =
                    make_float2(acc[mt][nt][0], acc[mt][nt][1]);
                *(float2*)(C + (size_t)(row + 8) * N + col) =
                    make_float2(acc[mt][nt][2], acc[mt][nt][3]);
            } else {
                *(float2*)(C + (size_t)row * N + col) =
                    make_float2(rtf32(acc[mt][nt][0]), rtf32(acc[mt][nt][1]));
                *(float2*)(C + (size_t)(row + 8) * N + col) =
                    make_float2(rtf32(acc[mt][nt][2]), rtf32(acc[mt][nt][3]));
            }
        }
    }
}

// ===========================================================================
// closed-form E8 argmin
// ===========================================================================
__global__ __launch_bounds__(256) void e8_argmin_fast() {
    int id = blockIdx.x * 256 + threadIdx.x;
    int t = id & (SEQ - 1), h = (id >> 11) & 15, b = id >> 15;
    size_t off = ((size_t)(b * SEQ + t)) * 128 + h * 8;
    float x[8];
#pragma unroll
    for (int j = 0; j < 8; j++) x[j] = g_coords[off + j] + g_coords2[off + j];

    int i1 = 0, i2 = -1;
    float m1 = fabsf(x[0]), m2 = -1.f;
#pragma unroll
    for (int j = 1; j < 8; j++) {
        float a = fabsf(x[j]);
        if (a > m1) { m2 = m1; i2 = i1; m1 = a; i1 = j; }
        else if (a > m2) { m2 = a; i2 = j; }
    }
    int a = min(i1, i2), bb = max(i1, i2);
    float dotp = m1 + m2;
    int p = a * 7 - (a * (a - 1)) / 2 + (bb - a - 1);
    int s = ((x[a] < 0.f) ? 2 : 0) | ((x[bb] < 0.f) ? 1 : 0);
    int idx_pair = p * 4 + s;

    float S = 0.f, mn = 3.4e38f;
    int mni = 0, mask = 0, cnt = 0;
#pragma unroll
    for (int j = 0; j < 8; j++) {
        float aa = fabsf(x[j]);
        S += aa;
        if (aa < mn) { mn = aa; mni = j; }
        if (x[j] < 0.f) { mask |= 1 << j; cnt++; }
    }
    if (cnt & 1) mask ^= (1 << mni);
    float doth = 0.5f * S - ((cnt & 1) ? mn : 0.f);

    g_idx[id] = (dotp >= doth) ? idx_pair : (112 + (mask >> 1));
}

// ===========================================================================
// attn_mid: FUSED rgemm + exp + running lp + partial PV + running P cumsum.
// ===========================================================================
#define AM_AS 0
#define AM_ES (64 * 68)
#define AM_K  (AM_ES + 64 * 68)
#define AM_V  (AM_K + 2 * 64 * 68)
#define AM_RS (AM_V + 2 * 64 * 72)
#define AM_RUN (AM_RS + 64)
#define AM_SMEM ((AM_RUN + 64) * 4)

__global__ __launch_bounds__(256) void attn_mid() {
    float* As = smf + AM_AS;
    float* Es = smf + AM_ES;
    float* rsum = smf + AM_RS;
    float* running = smf + AM_RUN;
    uint32_t sb = smem_u32(smf);

    int tid = threadIdx.x;
    int lane = tid & 31, w = tid >> 5;
    int lq = lane & 3, lr = lane >> 2;
    int wm = (w & 3) * 16, wt = (w >> 2) * 32;
    int m0 = blockIdx.x * 64, bh = blockIdx.y;
    int b = bh >> 4, h = bh & 15;

#pragma unroll
    for (int i = 0; i < 4; i++) {
        int idx = tid + i * 256;
        int r = idx >> 4, c4 = (idx & 15) * 4;
        int m = m0 + r;
        float4 a = (m < NROOT) ? *(const float4*)(g_RW + m * HDIM + c4)
                               : make_float4(0, 0, 0, 0);
        *(float4*)(As + r * 68 + c4) = a;
    }
    if (tid < 64) { running[tid] = 0.f; rsum[tid] = 0.f; }

    auto load_kv = [&](int j, int buf) {
        int t0 = j * 64;
#pragma unroll
        for (int i = 0; i < 4; i++) {
            int idx = tid + i * 256;
            int r = idx >> 4, c4 = (idx & 15) * 4;
            const float* kp = g_k + ((size_t)b * SEQ + t0 + r) * DMODEL + h * HDIM + c4;
            const float* vp = g_v + ((size_t)b * SEQ + t0 + r) * DMODEL + h * HDIM + c4;
            CP16(sb + (uint32_t)(AM_K + buf * 64 * 68 + r * 68 + c4) * 4, kp);
            CP16(sb + (uint32_t)(AM_V + buf * 64 * 72 + r * 72 + c4) * 4, vp);
        }
        CP_COMMIT();
    };
    load_kv(0, 0);

    float pacc[4][4];
#pragma unroll
    for (int nt = 0; nt < 4; nt++)
#pragma unroll
        for (int q = 0; q < 4; q++) pacc[nt][q] = 0.f;

    int mA = m0 + wm + lr, mB = mA + 8;

    for (int j = 0; j < NTILE; j++) {
        CP_WAIT(0);
        __syncthreads();
        if (j < NTILE - 1) load_kv(j + 1, (j + 1) & 1);

        const float* Kb = smf + AM_K + (j & 1) * 64 * 68;
        const float* Vb = smf + AM_V + (j & 1) * 64 * 72;
        int t0 = j * 64;

        float sacc[4][4];
#pragma unroll
        for (int nt = 0; nt < 4; nt++)
#pragma unroll
            for (int q = 0; q < 4; q++) sacc[nt][q] = 0.f;
#pragma unroll
        for (int ks = 0; ks < 8; ks++) {
            int kk = ks * 8;
            uint32_t a[4];
            a[0] = __float_as_uint(As[(wm + lr) * 68 + kk + lq]);
            a[1] = __float_as_uint(As[(wm + lr + 8) * 68 + kk + lq]);
            a[2] = __float_as_uint(As[(wm + lr) * 68 + kk + lq + 4]);
            a[3] = __float_as_uint(As[(wm + lr + 8) * 68 + kk + lq + 4]);
#pragma unroll
            for (int nt = 0; nt < 4; nt++) {
                int cc = wt + nt * 8 + lr;
                uint32_t bb[2];
                bb[0] = __float_as_uint(Kb[cc * 68 + kk + lq]);
                bb[1] = __float_as_uint(Kb[cc * 68 + kk + lq + 4]);
                MMA8(sacc[nt], a, bb);
            }
        }

        float sA = 0.f, sB = 0.f;
#pragma unroll
        for (int nt = 0; nt < 4; nt++) {
            float e0 = rtf32(__expf(sacc[nt][0]));
            float e1 = rtf32(__expf(sacc[nt][1]));
            float e2 = rtf32(__expf(sacc[nt][2]));
            float e3 = rtf32(__expf(sacc[nt][3]));
            sA += e0 + e1; sB += e2 + e3;
            int col = wt + nt * 8 + lq * 2;
            Es[(wm + lr) * 68 + col] = e0;
            Es[(wm + lr) * 68 + col + 1] = e1;
            Es[(wm + lr + 8) * 68 + col] = e2;
            Es[(wm + lr + 8) * 68 + col + 1] = e3;
            if (mA < NROOT)
                *(float2*)(g_E + ((size_t)bh * NROOT + mA) * SEQ + t0 + col) = make_float2(e0, e1);
            if (mB < NROOT)
                *(float2*)(g_E + ((size_t)bh * NROOT + mB) * SEQ + t0 + col) = make_float2(e2, e3);
        }
        sA += __shfl_xor_sync(0xffffffffu, sA, 1);
        sA += __shfl_xor_sync(0xffffffffu, sA, 2);
        sB += __shfl_xor_sync(0xffffffffu, sB, 1);
        sB += __shfl_xor_sync(0xffffffffu, sB, 2);
        if (lq == 0) {
            atomicAdd(&rsum[wm + lr], sA);
            atomicAdd(&rsum[wm + lr + 8], sB);
        }
        __syncthreads();

#pragma unroll
        for (int ks = 0; ks < 8; ks++) {
            int kk = ks * 8;
            uint32_t a[4];
            a[0] = __float_as_uint(Es[(wm + lr) * 68 + kk + lq]);
            a[1] = __float_as_uint(Es[(wm + lr + 8) * 68 + kk + lq]);
            a[2] = __float_as_uint(Es[(wm + lr) * 68 + kk + lq + 4]);
            a[3] = __float_as_uint(Es[(wm + lr + 8) * 68 + kk + lq + 4]);
#pragma unroll
            for (int nt = 0; nt < 4; nt++) {
                int cc = wt + nt * 8 + lr;
                uint32_t bb[2];
                bb[0] = __float_as_uint(Vb[(kk + lq) * 72 + cc]);
                bb[1] = __float_as_uint(Vb[(kk + lq + 4) * 72 + cc]);
                MMA8(pacc[nt], a, bb);
            }
        }

        if (tid < 64) {
            int m = m0 + tid;
            float r = running[tid] + rsum[tid];
            running[tid] = r;
            rsum[tid] = 0.f;
            if (m < NROOT) g_lp[(bh * NROOT + m) * NTILE + j] = r;
        }
        float* base = g_P + (size_t)(bh * NTILE + j) * NROOT * 64;
#pragma unroll
        for (int nt = 0; nt < 4; nt++) {
            int d = wt + nt * 8 + lq * 2;
            if (mA < NROOT) *(float2*)(base + mA * 64 + d) = make_float2(pacc[nt][0], pacc[nt][1]);
            if (mB < NROOT) *(float2*)(base + mB * 64 + d) = make_float2(pacc[nt][2], pacc[nt][3]);
        }
    }
}

// ===========================================================================
// attn_diag: diagonal tile via tf32 mma on causal-zeroed P, plus prefix add.
// ===========================================================================
__global__ __launch_bounds__(256) void attn_diag() {
    __shared__ float Ps[64 * 68];
    __shared__ float Vs[64 * 72];
    __shared__ float lsum[64];
    __shared__ int sidx[64];
    int tid = threadIdx.x;
    int lane = tid & 31, w = tid >> 5;
    int lq = lane & 3, lr = lane >> 2;
    int mblk = blockIdx.x, bh = blockIdx.y;
    int b = bh >> 4, h = bh & 15;
    int m0 = mblk * 64;
    if (tid < 64) sidx[tid] = g_idx[bh * SEQ + m0 + tid];
    __syncthreads();

#pragma unroll
    for (int k = 0; k < 4; k++) {
        int fl = tid + k * 256; int s = fl >> 4, c4 = (fl & 15) * 4;
        float4 v = *(const float4*)(g_v + ((size_t)b * SEQ + m0 + s) * DMODEL + h * HDIM + c4);
        *(float4*)(Vs + s * 72 + c4) = v;
    }
    {
        int row = tid >> 2, tg = tid & 3;
        const float* er = g_E + ((size_t)bh * NROOT + sidx[row]) * SEQ + m0 + tg * 16;
        float s = 0.f;
#pragma unroll
        for (int u = 0; u < 16; u++) {
            int sk = tg * 16 + u;
            float e = (sk <= row) ? er[u] : 0.f;
            Ps[row * 68 + sk] = e;
            s += e;
        }
        s += __shfl_xor_sync(0xffffffffu, s, 1);
        s += __shfl_xor_sync(0xffffffffu, s, 2);
        if (tg == 0) lsum[row] = s;
    }
    __syncthreads();

    int wm = (w & 3) * 16, wd = (w >> 2) * 32;
    float acc[4][4];
#pragma unroll
    for (int nt = 0; nt < 4; nt++)
#pragma unroll
        for (int q = 0; q < 4; q++) acc[nt][q] = 0.f;

#pragma unroll
    for (int ks = 0; ks < 8; ks++) {
        int kk = ks * 8;
        uint32_t a[4];
        a[0] = __float_as_uint(Ps[(wm + lr) * 68 + kk + lq]);
        a[1] = __float_as_uint(Ps[(wm + lr + 8) * 68 + kk + lq]);
        a[2] = __float_as_uint(Ps[(wm + lr) * 68 + kk + lq + 4]);
        a[3] = __float_as_uint(Ps[(wm + lr + 8) * 68 + kk + lq + 4]);
#pragma unroll
        for (int nt = 0; nt < 4; nt++) {
            int cc = wd + nt * 8 + lr;
            uint32_t bb[2];
            bb[0] = __float_as_uint(Vs[(kk + lq) * 72 + cc]);
            bb[1] = __float_as_uint(Vs[(kk + lq + 4) * 72 + cc]);
            MMA8(acc[nt], a, bb);
        }
    }

    int rA = wm + lr, rB = rA + 8;
    int rootA = sidx[rA], rootB = sidx[rB];
    float lA = lsum[rA], lB = lsum[rB];
    const float* cpA = nullptr;
    const float* cpB = nullptr;
    if (mblk > 0) {
        lA += g_lp[(bh * NROOT + rootA) * NTILE + mblk - 1];
        lB += g_lp[(bh * NROOT + rootB) * NTILE + mblk - 1];
        cpA = g_P + ((size_t)(bh * NTILE + mblk - 1) * NROOT + rootA) * 64;
        cpB = g_P + ((size_t)(bh * NTILE + mblk - 1) * NROOT + rootB) * 64;
    }
    float invA = 1.0f / lA, invB = 1.0f / lB;
    float* oA = g_o + ((size_t)b * SEQ + m0 + rA) * DMODEL + h * HDIM;
    float* oB = g_o + ((size_t)b * SEQ + m0 + rB) * DMODEL + h * HDIM;
#pragma unroll
    for (int nt = 0; nt < 4; nt++) {
        int d = wd + nt * 8 + lq * 2;
        float pa0 = 0.f, pa1 = 0.f, pb0 = 0.f, pb1 = 0.f;
        if (mblk > 0) {
            float2 t0 = *(const float2*)(cpA + d); pa0 = t0.x; pa1 = t0.y;
            float2 t1 = *(const float2*)(cpB + d); pb0 = t1.x; pb1 = t1.y;
        }
        *(float2*)(oA + d) = make_float2(rtf32((acc[nt][0] + pa0) * invA),
                                         rtf32((acc[nt][1] + pa1) * invA));
        *(float2*)(oB + d) = make_float2(rtf32((acc[nt][2] + pb0) * invB),
                                         rtf32((acc[nt][3] + pb1) * invB));
    }
}

// ---------------------------------------------------------------------------
// Launch
// ---------------------------------------------------------------------------
extern "C" void kernel_launch(void* const* d_in, const int* in_sizes, int n_in,
                              void* d_out, int out_size) {
    const float* x     = (const float*)d_in[0];
    const float* Wq    = (const float*)d_in[1];
    const float* Wk    = (const float*)d_in[2];
    const float* Wv    = (const float*)d_in[3];
    const float* Wte8  = (const float*)d_in[4];
    const float* Wfe8  = (const float*)d_in[5];
    const float* Wout  = (const float*)d_in[6];
    float* out = (float*)d_out;

    float *k, *v, *o, *coords, *coords2, *wqe8, *xr, *wkr, *wvr, *wor;
    cudaGetSymbolAddress((void**)&k, g_k);
    cudaGetSymbolAddress((void**)&v, g_v);
    cudaGetSymbolAddress((void**)&o, g_o);
    cudaGetSymbolAddress((void**)&coords, g_coords);
    cudaGetSymbolAddress((void**)&coords2, g_coords2);
    cudaGetSymbolAddress((void**)&wqe8, g_Wqe8);
    cudaGetSymbolAddress((void**)&xr, g_xr);
    cudaGetSymbolAddress((void**)&wkr, g_wkr);
    cudaGetSymbolAddress((void**)&wvr, g_wvr);
    cudaGetSymbolAddress((void**)&wor, g_wor);

    cudaFuncSetAttribute(gemm_mma<true>,  cudaFuncAttributeMaxDynamicSharedMemorySize, GM_SMEM_S);
    cudaFuncSetAttribute(gemm_mma<false>, cudaFuncAttributeMaxDynamicSharedMemorySize, GM_SMEM_T);
    cudaFuncSetAttribute(attn_mid, cudaFuncAttributeMaxDynamicSharedMemorySize, AM_SMEM);

    static cudaStream_t s2 = nullptr;
    static cudaEvent_t evF = nullptr, evJ = nullptr;
    if (s2 == nullptr) {
        cudaStreamCreateWithFlags(&s2, cudaStreamNonBlocking);
        cudaEventCreateWithFlags(&evF, cudaEventDisableTiming);
        cudaEventCreateWithFlags(&evJ, cudaEventDisableTiming);
    }

    // fused prep: x-round + weight transpose/round + Wqe8 + RW tables
    prep<<<PREP_BLKS, 256>>>(x, Wq, Wk, Wv, Wout, Wte8, Wfe8);

    // fork: coords (split-K, high precision) + argmin on side stream
    cudaEventRecord(evF, 0);
    cudaStreamWaitEvent(s2, evF, 0);
    gemm_mma<true><<<dim3(1, 32, 2), 128, GM_SMEM_S, s2>>>(
        x, wqe8, coords, wqe8 + 512 * 128, coords2, 128, 512, DMODEL, 512);
    e8_argmin_fast<<<256, 256, 0, s2>>>();
    cudaEventRecord(evJ, s2);

    // main stream: K/V then fused mid-chain (B operands are transposed weights)
    gemm_mma<false><<<dim3(8, 32, 2), 128, GM_SMEM_T>>>(
        xr, wkr, k, wvr, v, DMODEL, DMODEL, DMODEL, 0);

    attn_mid<<<dim3(4, NBH), 256, AM_SMEM>>>();

    // join: attn_diag needs g_idx
    cudaStreamWaitEvent(0, evJ, 0);
    attn_diag<<<dim3(32, NBH), 256>>>();

    // output projection
    gemm_mma<false><<<dim3(8, 32, 1), 128, GM_SMEM_T>>>(
        o, wor, out, wor, out, DMODEL, DMODEL, DMODEL, 0);
}

// round 15
// speedup vs baseline: 1.0739x; 1.0739x over previous
#include <cuda_runtime.h>
#include <cuda_bf16.h>
#include <math.h>
#include <stdint.h>

#define BATCH 2
#define SEQ   2048
#define DMODEL 1024
#define NHEAD 16
#define HDIM  64
#define MROWS (BATCH*SEQ)          // 4096
#define NBH   (BATCH*NHEAD)        // 32
#define NROOT 240
#define NTILE 32                   // key tiles of 64

// Scratch (device globals; no allocation allowed)
__device__ float g_k[MROWS*DMODEL];
__device__ float g_v[MROWS*DMODEL];
__device__ float g_o[MROWS*DMODEL];
__device__ float g_xr[MROWS*DMODEL];        // tf32-rounded x
__device__ float g_wkr[DMODEL*DMODEL];
__device__ float g_wvr[DMODEL*DMODEL];
__device__ float g_wor[DMODEL*DMODEL];
__device__ float g_P[NBH*NTILE*NROOT*64];   // CUMULATIVE per-tile PV partials
__device__ float g_lp[NBH*NROOT*NTILE];     // CUMULATIVE per-tile E-row sums
__device__ float g_coords[MROWS*128];
__device__ float g_coords2[MROWS*128];
__device__ int   g_idx[NBH*SEQ];
__device__ float g_Wqe8[DMODEL*128];
__device__ float g_RW[NROOT*HDIM];

// ===========================================================================
// helpers
// ===========================================================================
__device__ __forceinline__ uint32_t smem_u32(const void* p) {
    uint32_t a;
    asm("{ .reg .u64 t; cvta.to.shared.u64 t, %1; cvt.u32.u64 %0, t; }"
        : "=r"(a) : "l"(p));
    return a;
}
#define CP16(dst, src) \
    asm volatile("cp.async.cg.shared.global [%0], [%1], 16;" :: "r"(dst), "l"(src) : "memory")
#define CP_COMMIT() asm volatile("cp.async.commit_group;" ::: "memory")
#define CP_WAIT(n)  asm volatile("cp.async.wait_group %0;" :: "n"(n) : "memory")

__device__ __forceinline__ void cvt3(float x, uint32_t& hi, uint32_t& lo) {
    asm("cvt.rna.tf32.f32 %0, %1;" : "=r"(hi) : "f"(x));
    float r = x - __uint_as_float(hi);
    asm("cvt.rna.tf32.f32 %0, %1;" : "=r"(lo) : "f"(r));
}
__device__ __forceinline__ uint32_t cvt1(float x) {
    uint32_t t;
    asm("cvt.rna.tf32.f32 %0, %1;" : "=r"(t) : "f"(x));
    return t;
}
__device__ __forceinline__ float rtf32(float x) { return __uint_as_float(cvt1(x)); }

#define MMA8(c, a, b) \
    asm volatile("mma.sync.aligned.m16n8k8.row.col.f32.tf32.tf32.f32 " \
        "{%0,%1,%2,%3}, {%4,%5,%6,%7}, {%8,%9}, {%0,%1,%2,%3};" \
        : "+f"((c)[0]), "+f"((c)[1]), "+f"((c)[2]), "+f"((c)[3]) \
        : "r"((a)[0]), "r"((a)[1]), "r"((a)[2]), "r"((a)[3]), \
          "r"((b)[0]), "r"((b)[1]))

// ===========================================================================
// fused prep: round x, round Wk/Wv/Wout, build Wqe8, build RW tables
// ===========================================================================
#define PB_X (MROWS * DMODEL / 256)      // 16384
#define PB_W (DMODEL * DMODEL / 256)     // 4096
#define PB_Q 512
#define PB_T 8
#define PREP_BLKS (PB_X + 3 * PB_W + PB_Q + PB_T)

__global__ __launch_bounds__(256) void prep(const float* __restrict__ x,
                                            const float* __restrict__ Wq,
                                            const float* __restrict__ Wk,
                                            const float* __restrict__ Wv,
                                            const float* __restrict__ Wo,
                                            const float* __restrict__ Wt,
                                            const float* __restrict__ Wf) {
    int tid = threadIdx.x;
    int blk = blockIdx.x;
    if (blk < PB_X) {
        int i = blk * 256 + tid;
        g_xr[i] = rtf32(x[i]);
        return;
    }
    blk -= PB_X;
    if (blk < 3 * PB_W) {
        int sel = blk / PB_W;
        int i = (blk % PB_W) * 256 + tid;
        const float* s = (sel == 0) ? Wk : (sel == 1) ? Wv : Wo;
        float* d = (sel == 0) ? g_wkr : (sel == 1) ? g_wvr : g_wor;
        d[i] = rtf32(s[i]);
        return;
    }
    blk -= 3 * PB_W;
    if (blk < PB_Q) {
        int i = blk * 256 + tid;           // < 1024*128
        int in = i >> 7, c = i & 127, h = c >> 3, j = c & 7;
        float s = 0.f;
#pragma unroll
        for (int e = 0; e < 64; e++) s += Wq[(size_t)in * DMODEL + h * 64 + e] * Wt[e * 8 + j];
        g_Wqe8[i] = s;
        return;
    }
    blk -= PB_Q;
    {
        __shared__ float roots[NROOT * 8];
        for (int i = tid; i < NROOT * 8; i += 256) {
            int r = i >> 3, d = i & 7;
            float v;
            if (r < 112) {
                int p = r >> 2, s = r & 3;
                int a = 0, b = 1, cnt = 0; bool done = false;
                for (a = 0; a < 8 && !done; a++) {
                    for (b = a + 1; b < 8; b++) {
                        if (cnt == p) { done = true; break; }
                        cnt++;
                    }
                }
                a--;
                float si = (s & 2) ? -1.f : 1.f;
                float sj = (s & 1) ? -1.f : 1.f;
                v = (d == a) ? si : ((d == b) ? sj : 0.f);
            } else {
                int k = r - 112;
                int mask = (k << 1) | (__popc(k) & 1);
                v = ((mask >> d) & 1) ? -0.5f : 0.5f;
            }
            roots[i] = v;
        }
        __syncthreads();
        int base = blk * (NROOT * HDIM / PB_T);    // 1920 per block
        for (int t = tid; t < NROOT * HDIM / PB_T; t += 256) {
            int i = base + t;
            int r = i >> 6, d = i & 63;
            float s = 0.f;
#pragma unroll
            for (int j = 0; j < 8; j++) s += roots[r * 8 + j] * Wf[j * HDIM + d];
            g_RW[i] = rtf32(0.125f * s);
        }
    }
}

// ===========================================================================
// mma.sync tf32 GEMM (R13 scalar-LDS form, best known).
// 128 threads / 4 warps, warp tile 64x64.
// ===========================================================================
#define AS_STRIDE 36
#define BS_STRIDE 132
#define AS_F (128 * AS_STRIDE)
#define BS_F (32 * BS_STRIDE)
#define STG_F (AS_F + BS_F)
#define GM_SMEM (2 * STG_F * 4)

extern __shared__ float smf[];

template <bool SPLIT3>
__global__ __launch_bounds__(128, SPLIT3 ? 1 : 2)
void gemm_mma(const float* __restrict__ A,
              const float* __restrict__ B0, float* __restrict__ C0,
              const float* __restrict__ B1, float* __restrict__ C1,
              int N, int K, int lda, int koff) {
    const float* B = blockIdx.z ? B1 : B0;
    float* C = blockIdx.z ? C1 : C0;
    A += (size_t)blockIdx.z * koff;
    int tid = threadIdx.x;
    int lane = tid & 31, w = tid >> 5;
    int lq = lane & 3, lr = lane >> 2;
    int wm = (w & 1) * 64, wn = (w >> 1) * 64;
    int n0 = blockIdx.x * 128, m0 = blockIdx.y * 128;
    uint32_t sb = smem_u32(smf);

    float acc[4][8][4];
#pragma unroll
    for (int mt = 0; mt < 4; mt++)
#pragma unroll
        for (int nt = 0; nt < 8; nt++)
#pragma unroll
            for (int j = 0; j < 4; j++) acc[mt][nt][j] = 0.f;

    int ar[8], aq[8], bk[8], bn[8];
#pragma unroll
    for (int i = 0; i < 8; i++) {
        int idx = tid + i * 128;
        ar[i] = idx >> 3; aq[i] = idx & 7;
        bk[i] = idx >> 5; bn[i] = idx & 31;
    }

    auto issue_chunk = [&](int c) {
        int k0 = c * 32;
        uint32_t base = sb + (uint32_t)(c & 1) * (STG_F * 4);
#pragma unroll
        for (int i = 0; i < 8; i++)
            CP16(base + (uint32_t)(ar[i] * AS_STRIDE + aq[i] * 4) * 4,
                 A + (size_t)(m0 + ar[i]) * lda + k0 + aq[i] * 4);
#pragma unroll
        for (int i = 0; i < 8; i++)
            CP16(base + (uint32_t)(AS_F + bk[i] * BS_STRIDE + bn[i] * 4) * 4,
                 B + (size_t)(k0 + bk[i]) * N + n0 + bn[i] * 4);
        CP_COMMIT();
    };

    issue_chunk(0);
    int nchunk = K >> 5;

    for (int c = 0; c < nchunk; c++) {
        if (c < nchunk - 1) { issue_chunk(c + 1); CP_WAIT(1); }
        else                { CP_WAIT(0); }
        __syncthreads();

        const float* As = smf + (c & 1) * STG_F;
        const float* Bs = As + AS_F;

#pragma unroll
        for (int ks = 0; ks < 4; ks++) {
            int kk = ks * 8;
            uint32_t Ah[4][4], Al[4][4];
#pragma unroll
            for (int mt = 0; mt < 4; mt++) {
                int rb = wm + mt * 16 + lr;
                if (SPLIT3) {
                    cvt3(As[rb * AS_STRIDE + kk + lq],           Ah[mt][0], Al[mt][0]);
                    cvt3(As[(rb + 8) * AS_STRIDE + kk + lq],     Ah[mt][1], Al[mt][1]);
                    cvt3(As[rb * AS_STRIDE + kk + lq + 4],       Ah[mt][2], Al[mt][2]);
                    cvt3(As[(rb + 8) * AS_STRIDE + kk + lq + 4], Ah[mt][3], Al[mt][3]);
                } else {
                    Ah[mt][0] = __float_as_uint(As[rb * AS_STRIDE + kk + lq]);
                    Ah[mt][1] = __float_as_uint(As[(rb + 8) * AS_STRIDE + kk + lq]);
                    Ah[mt][2] = __float_as_uint(As[rb * AS_STRIDE + kk + lq + 4]);
                    Ah[mt][3] = __float_as_uint(As[(rb + 8) * AS_STRIDE + kk + lq + 4]);
                }
            }
            uint32_t Bh[8][2], Bl[8][2];
#pragma unroll
            for (int nt = 0; nt < 8; nt++) {
                int cc = wn + nt * 8 + lr;
                if (SPLIT3) {
                    cvt3(Bs[(kk + lq) * BS_STRIDE + cc],     Bh[nt][0], Bl[nt][0]);
                    cvt3(Bs[(kk + lq + 4) * BS_STRIDE + cc], Bh[nt][1], Bl[nt][1]);
                } else {
                    Bh[nt][0] = __float_as_uint(Bs[(kk + lq) * BS_STRIDE + cc]);
                    Bh[nt][1] = __float_as_uint(Bs[(kk + lq + 4) * BS_STRIDE + cc]);
                }
            }
#pragma unroll
            for (int mt = 0; mt < 4; mt++)
#pragma unroll
                for (int nt = 0; nt < 8; nt++) {
                    MMA8(acc[mt][nt], Ah[mt], Bh[nt]);
                    if (SPLIT3) {
                        MMA8(acc[mt][nt], Al[mt], Bh[nt]);
                        MMA8(acc[mt][nt], Ah[mt], Bl[nt]);
                    }
                }
        }
        __syncthreads();
    }

#pragma unroll
    for (int mt = 0; mt < 4; mt++) {
        int row = m0 + wm + mt * 16 + lr;
#pragma unroll
        for (int nt = 0; nt < 8; nt++) {
            int col = n0 + wn + nt * 8 + lq * 2;
            if (SPLIT3) {
                *(float2*)(C + (size_t)row * N + col) =
                    make_float2(acc[mt][nt][0], acc[mt][nt][1]);
                *(float2*)(C + (size_t)(row + 8) * N + col) =
                    make_float2(acc[mt][nt][2], acc[mt][nt][3]);
            } else {
                *(float2*)(C + (size_t)row * N + col) =
                    make_float2(rtf32(acc[mt][nt][0]), rtf32(acc[mt][nt][1]));
                *(float2*)(C + (size_t)(row + 8) * N + col) =
                    make_float2(rtf32(acc[mt][nt][2]), rtf32(acc[mt][nt][3]));
            }
        }
    }
}

// ===========================================================================
// closed-form E8 argmin
// ===========================================================================
__global__ __launch_bounds__(256) void e8_argmin_fast() {
    int id = blockIdx.x * 256 + threadIdx.x;
    int t = id & (SEQ - 1), h = (id >> 11) & 15, b = id >> 15;
    size_t off = ((size_t)(b * SEQ + t)) * 128 + h * 8;
    float x[8];
#pragma unroll
    for (int j = 0; j < 8; j++) x[j] = g_coords[off + j] + g_coords2[off + j];

    int i1 = 0, i2 = -1;
    float m1 = fabsf(x[0]), m2 = -1.f;
#pragma unroll
    for (int j = 1; j < 8; j++) {
        float a = fabsf(x[j]);
        if (a > m1) { m2 = m1; i2 = i1; m1 = a; i1 = j; }
        else if (a > m2) { m2 = a; i2 = j; }
    }
    int a = min(i1, i2), bb = max(i1, i2);
    float dotp = m1 + m2;
    int p = a * 7 - (a * (a - 1)) / 2 + (bb - a - 1);
    int s = ((x[a] < 0.f) ? 2 : 0) | ((x[bb] < 0.f) ? 1 : 0);
    int idx_pair = p * 4 + s;

    float S = 0.f, mn = 3.4e38f;
    int mni = 0, mask = 0, cnt = 0;
#pragma unroll
    for (int j = 0; j < 8; j++) {
        float aa = fabsf(x[j]);
        S += aa;
        if (aa < mn) { mn = aa; mni = j; }
        if (x[j] < 0.f) { mask |= 1 << j; cnt++; }
    }
    if (cnt & 1) mask ^= (1 << mni);
    float doth = 0.5f * S - ((cnt & 1) ? mn : 0.f);

    g_idx[id] = (dotp >= doth) ? idx_pair : (112 + (mask >> 1));
}

// ===========================================================================
// attn_mid: FUSED rgemm + exp + running lp + partial PV + running P cumsum.
// NO gmem E stores anymore (attn_diag recomputes its diagonal tile).
// ===========================================================================
#define AM_AS 0
#define AM_ES (64 * 68)
#define AM_K  (AM_ES + 64 * 68)
#define AM_V  (AM_K + 2 * 64 * 68)
#define AM_RS (AM_V + 2 * 64 * 72)
#define AM_RUN (AM_RS + 64)
#define AM_SMEM ((AM_RUN + 64) * 4)

__global__ __launch_bounds__(256) void attn_mid() {
    float* As = smf + AM_AS;
    float* Es = smf + AM_ES;
    float* rsum = smf + AM_RS;
    float* running = smf + AM_RUN;
    uint32_t sb = smem_u32(smf);

    int tid = threadIdx.x;
    int lane = tid & 31, w = tid >> 5;
    int lq = lane & 3, lr = lane >> 2;
    int wm = (w & 3) * 16, wt = (w >> 2) * 32;
    int m0 = blockIdx.x * 64, bh = blockIdx.y;
    int b = bh >> 4, h = bh & 15;

#pragma unroll
    for (int i = 0; i < 4; i++) {
        int idx = tid + i * 256;
        int r = idx >> 4, c4 = (idx & 15) * 4;
        int m = m0 + r;
        float4 a = (m < NROOT) ? *(const float4*)(g_RW + m * HDIM + c4)
                               : make_float4(0, 0, 0, 0);
        *(float4*)(As + r * 68 + c4) = a;
    }
    if (tid < 64) { running[tid] = 0.f; rsum[tid] = 0.f; }

    auto load_kv = [&](int j, int buf) {
        int t0 = j * 64;
#pragma unroll
        for (int i = 0; i < 4; i++) {
            int idx = tid + i * 256;
            int r = idx >> 4, c4 = (idx & 15) * 4;
            const float* kp = g_k + ((size_t)b * SEQ + t0 + r) * DMODEL + h * HDIM + c4;
            const float* vp = g_v + ((size_t)b * SEQ + t0 + r) * DMODEL + h * HDIM + c4;
            CP16(sb + (uint32_t)(AM_K + buf * 64 * 68 + r * 68 + c4) * 4, kp);
            CP16(sb + (uint32_t)(AM_V + buf * 64 * 72 + r * 72 + c4) * 4, vp);
        }
        CP_COMMIT();
    };
    load_kv(0, 0);

    float pacc[4][4];
#pragma unroll
    for (int nt = 0; nt < 4; nt++)
#pragma unroll
        for (int q = 0; q < 4; q++) pacc[nt][q] = 0.f;

    int mA = m0 + wm + lr, mB = mA + 8;

    for (int j = 0; j < NTILE; j++) {
        CP_WAIT(0);
        __syncthreads();   // all threads done with iteration j-1 (incl. PV reads)
        if (j < NTILE - 1) load_kv(j + 1, (j + 1) & 1);

        const float* Kb = smf + AM_K + (j & 1) * 64 * 68;
        const float* Vb = smf + AM_V + (j & 1) * 64 * 72;

        float sacc[4][4];
#pragma unroll
        for (int nt = 0; nt < 4; nt++)
#pragma unroll
            for (int q = 0; q < 4; q++) sacc[nt][q] = 0.f;
#pragma unroll
        for (int ks = 0; ks < 8; ks++) {
            int kk = ks * 8;
            uint32_t a[4];
            a[0] = __float_as_uint(As[(wm + lr) * 68 + kk + lq]);
            a[1] = __float_as_uint(As[(wm + lr + 8) * 68 + kk + lq]);
            a[2] = __float_as_uint(As[(wm + lr) * 68 + kk + lq + 4]);
            a[3] = __float_as_uint(As[(wm + lr + 8) * 68 + kk + lq + 4]);
#pragma unroll
            for (int nt = 0; nt < 4; nt++) {
                int cc = wt + nt * 8 + lr;
                uint32_t bb[2];
                bb[0] = __float_as_uint(Kb[cc * 68 + kk + lq]);
                bb[1] = __float_as_uint(Kb[cc * 68 + kk + lq + 4]);
                MMA8(sacc[nt], a, bb);
            }
        }

        float sA = 0.f, sB = 0.f;
#pragma unroll
        for (int nt = 0; nt < 4; nt++) {
            float e0 = rtf32(__expf(sacc[nt][0]));
            float e1 = rtf32(__expf(sacc[nt][1]));
            float e2 = rtf32(__expf(sacc[nt][2]));
            float e3 = rtf32(__expf(sacc[nt][3]));
            sA += e0 + e1; sB += e2 + e3;
            int col = wt + nt * 8 + lq * 2;
            Es[(wm + lr) * 68 + col] = e0;
            Es[(wm + lr) * 68 + col + 1] = e1;
            Es[(wm + lr + 8) * 68 + col] = e2;
            Es[(wm + lr + 8) * 68 + col + 1] = e3;
        }
        sA += __shfl_xor_sync(0xffffffffu, sA, 1);
        sA += __shfl_xor_sync(0xffffffffu, sA, 2);
        sB += __shfl_xor_sync(0xffffffffu, sB, 1);
        sB += __shfl_xor_sync(0xffffffffu, sB, 2);
        if (lq == 0) {
            atomicAdd(&rsum[wm + lr], sA);
            atomicAdd(&rsum[wm + lr + 8], sB);
        }
        __syncthreads();   // Es + rsum visible

#pragma unroll
        for (int ks = 0; ks < 8; ks++) {
            int kk = ks * 8;
            uint32_t a[4];
            a[0] = __float_as_uint(Es[(wm + lr) * 68 + kk + lq]);
            a[1] = __float_as_uint(Es[(wm + lr + 8) * 68 + kk + lq]);
            a[2] = __float_as_uint(Es[(wm + lr) * 68 + kk + lq + 4]);
            a[3] = __float_as_uint(Es[(wm + lr + 8) * 68 + kk + lq + 4]);
#pragma unroll
            for (int nt = 0; nt < 4; nt++) {
                int cc = wt + nt * 8 + lr;
                uint32_t bb[2];
                bb[0] = __float_as_uint(Vb[(kk + lq) * 72 + cc]);
                bb[1] = __float_as_uint(Vb[(kk + lq + 4) * 72 + cc]);
                MMA8(pacc[nt], a, bb);
            }
        }

        if (tid < 64) {
            int m = m0 + tid;
            float r = running[tid] + rsum[tid];
            running[tid] = r;
            rsum[tid] = 0.f;
            if (m < NROOT) g_lp[(bh * NROOT + m) * NTILE + j] = r;
        }
        float* base = g_P + (size_t)(bh * NTILE + j) * NROOT * 64;
#pragma unroll
        for (int nt = 0; nt < 4; nt++) {
            int d = wt + nt * 8 + lq * 2;
            if (mA < NROOT) *(float2*)(base + mA * 64 + d) = make_float2(pacc[nt][0], pacc[nt][1]);
            if (mB < NROOT) *(float2*)(base + mB * 64 + d) = make_float2(pacc[nt][2], pacc[nt][3]);
        }
    }
}

// ===========================================================================
// attn_diag: recompute diagonal S from gathered RW rows + diagonal K tile,
// exp + causal zero + rowsum, PV mma, add cumulative prefix. No g_E.
// ===========================================================================
__global__ __launch_bounds__(256) void attn_diag() {
    __shared__ float RWs[64 * 68];   // RW rows gathered by sidx  [q][d]
    __shared__ float Kd[64 * 68];    // diagonal K tile           [k][d]
    __shared__ float Ps[64 * 68];    // causal-zeroed exp(S)      [q][k]
    __shared__ float Vs[64 * 72];    // diagonal V tile           [k][d]
    __shared__ float rsum[64];
    __shared__ int sidx[64];
    int tid = threadIdx.x;
    int lane = tid & 31, w = tid >> 5;
    int lq = lane & 3, lr = lane >> 2;
    int wm = (w & 3) * 16, wt = (w >> 2) * 32;
    int mblk = blockIdx.x, bh = blockIdx.y;
    int b = bh >> 4, h = bh & 15;
    int m0 = mblk * 64;
    if (tid < 64) { sidx[tid] = g_idx[bh * SEQ + m0 + tid]; rsum[tid] = 0.f; }
    __syncthreads();

    // gather RW rows + load K/V diag tiles
#pragma unroll
    for (int i = 0; i < 4; i++) {
        int idx = tid + i * 256;
        int r = idx >> 4, c4 = (idx & 15) * 4;
        *(float4*)(RWs + r * 68 + c4) = *(const float4*)(g_RW + sidx[r] * HDIM + c4);
        float4 kk = *(const float4*)(g_k + ((size_t)b * SEQ + m0 + r) * DMODEL + h * HDIM + c4);
        *(float4*)(Kd + r * 68 + c4) = kk;
        float4 vv = *(const float4*)(g_v + ((size_t)b * SEQ + m0 + r) * DMODEL + h * HDIM + c4);
        *(float4*)(Vs + r * 72 + c4) = vv;
    }
    __syncthreads();

    // S = RWs x Kd^T
    float sacc[4][4];
#pragma unroll
    for (int nt = 0; nt < 4; nt++)
#pragma unroll
        for (int q = 0; q < 4; q++) sacc[nt][q] = 0.f;
#pragma unroll
    for (int ks = 0; ks < 8; ks++) {
        int kk = ks * 8;
        uint32_t a[4];
        a[0] = __float_as_uint(RWs[(wm + lr) * 68 + kk + lq]);
        a[1] = __float_as_uint(RWs[(wm + lr + 8) * 68 + kk + lq]);
        a[2] = __float_as_uint(RWs[(wm + lr) * 68 + kk + lq + 4]);
        a[3] = __float_as_uint(RWs[(wm + lr + 8) * 68 + kk + lq + 4]);
#pragma unroll
        for (int nt = 0; nt < 4; nt++) {
            int cc = wt + nt * 8 + lr;
            uint32_t bb[2];
            bb[0] = __float_as_uint(Kd[cc * 68 + kk + lq]);
            bb[1] = __float_as_uint(Kd[cc * 68 + kk + lq + 4]);
            MMA8(sacc[nt], a, bb);
        }
    }

    // exp + causal zero + smem store + rowsums
    {
        int qA = wm + lr, qB = qA + 8;
        float sA = 0.f, sB = 0.f;
#pragma unroll
        for (int nt = 0; nt < 4; nt++) {
            int col = wt + nt * 8 + lq * 2;
            float e0 = (col     <= qA) ? rtf32(__expf(sacc[nt][0])) : 0.f;
            float e1 = (col + 1 <= qA) ? rtf32(__expf(sacc[nt][1])) : 0.f;
            float e2 = (col     <= qB) ? rtf32(__expf(sacc[nt][2])) : 0.f;
            float e3 = (col + 1 <= qB) ? rtf32(__expf(sacc[nt][3])) : 0.f;
            sA += e0 + e1; sB += e2 + e3;
            Ps[qA * 68 + col] = e0;
            Ps[qA * 68 + col + 1] = e1;
            Ps[qB * 68 + col] = e2;
            Ps[qB * 68 + col + 1] = e3;
        }
        sA += __shfl_xor_sync(0xffffffffu, sA, 1);
        sA += __shfl_xor_sync(0xffffffffu, sA, 2);
        sB += __shfl_xor_sync(0xffffffffu, sB, 1);
        sB += __shfl_xor_sync(0xffffffffu, sB, 2);
        if (lq == 0) {
            atomicAdd(&rsum[qA], sA);
            atomicAdd(&rsum[qB], sB);
        }
    }
    __syncthreads();

    // O_diag = Ps x Vs
    float acc[4][4];
#pragma unroll
    for (int nt = 0; nt < 4; nt++)
#pragma unroll
        for (int q = 0; q < 4; q++) acc[nt][q] = 0.f;
#pragma unroll
    for (int ks = 0; ks < 8; ks++) {
        int kk = ks * 8;
        uint32_t a[4];
        a[0] = __float_as_uint(Ps[(wm + lr) * 68 + kk + lq]);
        a[1] = __float_as_uint(Ps[(wm + lr + 8) * 68 + kk + lq]);
        a[2] = __float_as_uint(Ps[(wm + lr) * 68 + kk + lq + 4]);
        a[3] = __float_as_uint(Ps[(wm + lr + 8) * 68 + kk + lq + 4]);
#pragma unroll
        for (int nt = 0; nt < 4; nt++) {
            int cc = wt + nt * 8 + lr;
            uint32_t bb[2];
            bb[0] = __float_as_uint(Vs[(kk + lq) * 72 + cc]);
            bb[1] = __float_as_uint(Vs[(kk + lq + 4) * 72 + cc]);
            MMA8(acc[nt], a, bb);
        }
    }

    int rA = wm + lr, rB = rA + 8;
    int rootA = sidx[rA], rootB = sidx[rB];
    float lA = rsum[rA], lB = rsum[rB];
    const float* cpA = nullptr;
    const float* cpB = nullptr;
    if (mblk > 0) {
        lA += g_lp[(bh * NROOT + rootA) * NTILE + mblk - 1];
        lB += g_lp[(bh * NROOT + rootB) * NTILE + mblk - 1];
        cpA = g_P + ((size_t)(bh * NTILE + mblk - 1) * NROOT + rootA) * 64;
        cpB = g_P + ((size_t)(bh * NTILE + mblk - 1) * NROOT + rootB) * 64;
    }
    float invA = 1.0f / lA, invB = 1.0f / lB;
    float* oA = g_o + ((size_t)b * SEQ + m0 + rA) * DMODEL + h * HDIM;
    float* oB = g_o + ((size_t)b * SEQ + m0 + rB) * DMODEL + h * HDIM;
#pragma unroll
    for (int nt = 0; nt < 4; nt++) {
        int d = wt + nt * 8 + lq * 2;
        float pa0 = 0.f, pa1 = 0.f, pb0 = 0.f, pb1 = 0.f;
        if (mblk > 0) {
            float2 t0 = *(const float2*)(cpA + d); pa0 = t0.x; pa1 = t0.y;
            float2 t1 = *(const float2*)(cpB + d); pb0 = t1.x; pb1 = t1.y;
        }
        *(float2*)(oA + d) = make_float2(rtf32((acc[nt][0] + pa0) * invA),
                                         rtf32((acc[nt][1] + pa1) * invA));
        *(float2*)(oB + d) = make_float2(rtf32((acc[nt][2] + pb0) * invB),
                                         rtf32((acc[nt][3] + pb1) * invB));
    }
}

// ---------------------------------------------------------------------------
// Launch
// ---------------------------------------------------------------------------
extern "C" void kernel_launch(void* const* d_in, const int* in_sizes, int n_in,
                              void* d_out, int out_size) {
    const float* x     = (const float*)d_in[0];
    const float* Wq    = (const float*)d_in[1];
    const float* Wk    = (const float*)d_in[2];
    const float* Wv    = (const float*)d_in[3];
    const float* Wte8  = (const float*)d_in[4];
    const float* Wfe8  = (const float*)d_in[5];
    const float* Wout  = (const float*)d_in[6];
    float* out = (float*)d_out;

    float *k, *v, *o, *coords, *coords2, *wqe8, *xr, *wkr, *wvr, *wor;
    cudaGetSymbolAddress((void**)&k, g_k);
    cudaGetSymbolAddress((void**)&v, g_v);
    cudaGetSymbolAddress((void**)&o, g_o);
    cudaGetSymbolAddress((void**)&coords, g_coords);
    cudaGetSymbolAddress((void**)&coords2, g_coords2);
    cudaGetSymbolAddress((void**)&wqe8, g_Wqe8);
    cudaGetSymbolAddress((void**)&xr, g_xr);
    cudaGetSymbolAddress((void**)&wkr, g_wkr);
    cudaGetSymbolAddress((void**)&wvr, g_wvr);
    cudaGetSymbolAddress((void**)&wor, g_wor);

    cudaFuncSetAttribute(gemm_mma<true>,  cudaFuncAttributeMaxDynamicSharedMemorySize, GM_SMEM);
    cudaFuncSetAttribute(gemm_mma<false>, cudaFuncAttributeMaxDynamicSharedMemorySize, GM_SMEM);
    cudaFuncSetAttribute(attn_mid, cudaFuncAttributeMaxDynamicSharedMemorySize, AM_SMEM);

    static cudaStream_t s2 = nullptr;
    static cudaEvent_t evF = nullptr, evJ = nullptr;
    if (s2 == nullptr) {
        cudaStreamCreateWithFlags(&s2, cudaStreamNonBlocking);
        cudaEventCreateWithFlags(&evF, cudaEventDisableTiming);
        cudaEventCreateWithFlags(&evJ, cudaEventDisableTiming);
    }

    // fused prep
    prep<<<PREP_BLKS, 256>>>(x, Wq, Wk, Wv, Wout, Wte8, Wfe8);

    // fork: coords (split-K, high precision) + argmin on side stream
    cudaEventRecord(evF, 0);
    cudaStreamWaitEvent(s2, evF, 0);
    gemm_mma<true><<<dim3(1, 32, 2), 128, GM_SMEM, s2>>>(
        x, wqe8, coords, wqe8 + 512 * 128, coords2, 128, 512, DMODEL, 512);
    e8_argmin_fast<<<256, 256, 0, s2>>>();
    cudaEventRecord(evJ, s2);

    // main stream: K/V then fused mid-chain
    gemm_mma<false><<<dim3(8, 32, 2), 128, GM_SMEM>>>(
        xr, wkr, k, wvr, v, DMODEL, DMODEL, DMODEL, 0);

    attn_mid<<<dim3(4, NBH), 256, AM_SMEM>>>();

    // join: attn_diag needs g_idx
    cudaStreamWaitEvent(0, evJ, 0);
    attn_diag<<<dim3(32, NBH), 256>>>();

    // output projection
    gemm_mma<false><<<dim3(8, 32, 1), 128, GM_SMEM>>>(
        o, wor, out, wor, out, DMODEL, DMODEL, DMODEL, 0);
}

// round 16
// speedup vs baseline: 1.0802x; 1.0059x over previous
#include <cuda_runtime.h>
#include <cuda_bf16.h>
#include <math.h>
#include <stdint.h>

#define BATCH 2
#define SEQ   2048
#define DMODEL 1024
#define NHEAD 16
#define HDIM  64
#define MROWS (BATCH*SEQ)          // 4096
#define NBH   (BATCH*NHEAD)        // 32
#define NROOT 240
#define NTILE 32                   // key tiles of 64

// Scratch (device globals; no allocation allowed)
__device__ float g_k[MROWS*DMODEL];
__device__ float g_v[MROWS*DMODEL];
__device__ float g_o[MROWS*DMODEL];
__device__ float g_xr[MROWS*DMODEL];        // tf32-rounded x
__device__ float g_wkr[DMODEL*DMODEL];
__device__ float g_wvr[DMODEL*DMODEL];
__device__ float g_wor[DMODEL*DMODEL];
__device__ float g_P[NBH*NTILE*NROOT*64];   // CUMULATIVE per-tile PV partials
__device__ float g_lp[NBH*NROOT*NTILE];     // CUMULATIVE per-tile E-row sums
__device__ float g_coords[MROWS*128];
__device__ float g_coords2[MROWS*128];
__device__ int   g_idx[NBH*SEQ];
__device__ float g_Wqe8[DMODEL*128];
__device__ float g_RW[NROOT*HDIM];

// ===========================================================================
// helpers
// ===========================================================================
__device__ __forceinline__ uint32_t smem_u32(const void* p) {
    uint32_t a;
    asm("{ .reg .u64 t; cvta.to.shared.u64 t, %1; cvt.u32.u64 %0, t; }"
        : "=r"(a) : "l"(p));
    return a;
}
#define CP16(dst, src) \
    asm volatile("cp.async.cg.shared.global [%0], [%1], 16;" :: "r"(dst), "l"(src) : "memory")
#define CP_COMMIT() asm volatile("cp.async.commit_group;" ::: "memory")
#define CP_WAIT(n)  asm volatile("cp.async.wait_group %0;" :: "n"(n) : "memory")

__device__ __forceinline__ void cvt3(float x, uint32_t& hi, uint32_t& lo) {
    asm("cvt.rna.tf32.f32 %0, %1;" : "=r"(hi) : "f"(x));
    float r = x - __uint_as_float(hi);
    asm("cvt.rna.tf32.f32 %0, %1;" : "=r"(lo) : "f"(r));
}
__device__ __forceinline__ uint32_t cvt1(float x) {
    uint32_t t;
    asm("cvt.rna.tf32.f32 %0, %1;" : "=r"(t) : "f"(x));
    return t;
}
__device__ __forceinline__ float rtf32(float x) { return __uint_as_float(cvt1(x)); }

#define MMA8(c, a, b) \
    asm volatile("mma.sync.aligned.m16n8k8.row.col.f32.tf32.tf32.f32 " \
        "{%0,%1,%2,%3}, {%4,%5,%6,%7}, {%8,%9}, {%0,%1,%2,%3};" \
        : "+f"((c)[0]), "+f"((c)[1]), "+f"((c)[2]), "+f"((c)[3]) \
        : "r"((a)[0]), "r"((a)[1]), "r"((a)[2]), "r"((a)[3]), \
          "r"((b)[0]), "r"((b)[1]))

// ===========================================================================
// fused prep: round x, round Wk/Wv/Wout, build Wqe8, build RW tables
// ===========================================================================
#define PB_X (MROWS * DMODEL / 256)      // 16384
#define PB_W (DMODEL * DMODEL / 256)     // 4096
#define PB_Q 512
#define PB_T 8
#define PREP_BLKS (PB_X + 3 * PB_W + PB_Q + PB_T)

__global__ __launch_bounds__(256) void prep(const float* __restrict__ x,
                                            const float* __restrict__ Wq,
                                            const float* __restrict__ Wk,
                                            const float* __restrict__ Wv,
                                            const float* __restrict__ Wo,
                                            const float* __restrict__ Wt,
                                            const float* __restrict__ Wf) {
    int tid = threadIdx.x;
    int blk = blockIdx.x;
    if (blk < PB_X) {
        int i = blk * 256 + tid;
        g_xr[i] = rtf32(x[i]);
        return;
    }
    blk -= PB_X;
    if (blk < 3 * PB_W) {
        int sel = blk / PB_W;
        int i = (blk % PB_W) * 256 + tid;
        const float* s = (sel == 0) ? Wk : (sel == 1) ? Wv : Wo;
        float* d = (sel == 0) ? g_wkr : (sel == 1) ? g_wvr : g_wor;
        d[i] = rtf32(s[i]);
        return;
    }
    blk -= 3 * PB_W;
    if (blk < PB_Q) {
        int i = blk * 256 + tid;           // < 1024*128
        int in = i >> 7, c = i & 127, h = c >> 3, j = c & 7;
        float s = 0.f;
#pragma unroll
        for (int e = 0; e < 64; e++) s += Wq[(size_t)in * DMODEL + h * 64 + e] * Wt[e * 8 + j];
        g_Wqe8[i] = s;
        return;
    }
    blk -= PB_Q;
    {
        __shared__ float roots[NROOT * 8];
        for (int i = tid; i < NROOT * 8; i += 256) {
            int r = i >> 3, d = i & 7;
            float v;
            if (r < 112) {
                int p = r >> 2, s = r & 3;
                int a = 0, b = 1, cnt = 0; bool done = false;
                for (a = 0; a < 8 && !done; a++) {
                    for (b = a + 1; b < 8; b++) {
                        if (cnt == p) { done = true; break; }
                        cnt++;
                    }
                }
                a--;
                float si = (s & 2) ? -1.f : 1.f;
                float sj = (s & 1) ? -1.f : 1.f;
                v = (d == a) ? si : ((d == b) ? sj : 0.f);
            } else {
                int k = r - 112;
                int mask = (k << 1) | (__popc(k) & 1);
                v = ((mask >> d) & 1) ? -0.5f : 0.5f;
            }
            roots[i] = v;
        }
        __syncthreads();
        int base = blk * (NROOT * HDIM / PB_T);    // 1920 per block
        for (int t = tid; t < NROOT * HDIM / PB_T; t += 256) {
            int i = base + t;
            int r = i >> 6, d = i & 63;
            float s = 0.f;
#pragma unroll
            for (int j = 0; j < 8; j++) s += roots[r * 8 + j] * Wf[j * HDIM + d];
            g_RW[i] = rtf32(0.125f * s);
        }
    }
}

// ===========================================================================
// mma.sync tf32 GEMM. BS_STRIDE = 136 (== 8 mod 32) -> B-fragment reads
// bank-conflict-free (8*lq + lr covers all 32 banks). Was 132 (2-way).
// 128 threads / 4 warps, warp tile 64x64.
// ===========================================================================
#define AS_STRIDE 36
#define BS_STRIDE 136
#define AS_F (128 * AS_STRIDE)           // 4608
#define BS_F (32 * BS_STRIDE)            // 4352
#define STG_F (AS_F + BS_F)              // 8960 floats
#define GM_SMEM (2 * STG_F * 4)          // 71680 B

extern __shared__ float smf[];

template <bool SPLIT3>
__global__ __launch_bounds__(128, SPLIT3 ? 1 : 2)
void gemm_mma(const float* __restrict__ A,
              const float* __restrict__ B0, float* __restrict__ C0,
              const float* __restrict__ B1, float* __restrict__ C1,
              int N, int K, int lda, int koff) {
    const float* B = blockIdx.z ? B1 : B0;
    float* C = blockIdx.z ? C1 : C0;
    A += (size_t)blockIdx.z * koff;
    int tid = threadIdx.x;
    int lane = tid & 31, w = tid >> 5;
    int lq = lane & 3, lr = lane >> 2;
    int wm = (w & 1) * 64, wn = (w >> 1) * 64;
    int n0 = blockIdx.x * 128, m0 = blockIdx.y * 128;
    uint32_t sb = smem_u32(smf);

    float acc[4][8][4];
#pragma unroll
    for (int mt = 0; mt < 4; mt++)
#pragma unroll
        for (int nt = 0; nt < 8; nt++)
#pragma unroll
            for (int j = 0; j < 4; j++) acc[mt][nt][j] = 0.f;

    int ar[8], aq[8], bk[8], bn[8];
#pragma unroll
    for (int i = 0; i < 8; i++) {
        int idx = tid + i * 128;
        ar[i] = idx >> 3; aq[i] = idx & 7;
        bk[i] = idx >> 5; bn[i] = idx & 31;
    }

    auto issue_chunk = [&](int c) {
        int k0 = c * 32;
        uint32_t base = sb + (uint32_t)(c & 1) * (STG_F * 4);
#pragma unroll
        for (int i = 0; i < 8; i++)
            CP16(base + (uint32_t)(ar[i] * AS_STRIDE + aq[i] * 4) * 4,
                 A + (size_t)(m0 + ar[i]) * lda + k0 + aq[i] * 4);
#pragma unroll
        for (int i = 0; i < 8; i++)
            CP16(base + (uint32_t)(AS_F + bk[i] * BS_STRIDE + bn[i] * 4) * 4,
                 B + (size_t)(k0 + bk[i]) * N + n0 + bn[i] * 4);
        CP_COMMIT();
    };

    issue_chunk(0);
    int nchunk = K >> 5;

    for (int c = 0; c < nchunk; c++) {
        if (c < nchunk - 1) { issue_chunk(c + 1); CP_WAIT(1); }
        else                { CP_WAIT(0); }
        __syncthreads();

        const float* As = smf + (c & 1) * STG_F;
        const float* Bs = As + AS_F;

#pragma unroll
        for (int ks = 0; ks < 4; ks++) {
            int kk = ks * 8;
            uint32_t Ah[4][4], Al[4][4];
#pragma unroll
            for (int mt = 0; mt < 4; mt++) {
                int rb = wm + mt * 16 + lr;
                if (SPLIT3) {
                    cvt3(As[rb * AS_STRIDE + kk + lq],           Ah[mt][0], Al[mt][0]);
                    cvt3(As[(rb + 8) * AS_STRIDE + kk + lq],     Ah[mt][1], Al[mt][1]);
                    cvt3(As[rb * AS_STRIDE + kk + lq + 4],       Ah[mt][2], Al[mt][2]);
                    cvt3(As[(rb + 8) * AS_STRIDE + kk + lq + 4], Ah[mt][3], Al[mt][3]);
                } else {
                    Ah[mt][0] = __float_as_uint(As[rb * AS_STRIDE + kk + lq]);
                    Ah[mt][1] = __float_as_uint(As[(rb + 8) * AS_STRIDE + kk + lq]);
                    Ah[mt][2] = __float_as_uint(As[rb * AS_STRIDE + kk + lq + 4]);
                    Ah[mt][3] = __float_as_uint(As[(rb + 8) * AS_STRIDE + kk + lq + 4]);
                }
            }
            uint32_t Bh[8][2], Bl[8][2];
#pragma unroll
            for (int nt = 0; nt < 8; nt++) {
                int cc = wn + nt * 8 + lr;
                if (SPLIT3) {
                    cvt3(Bs[(kk + lq) * BS_STRIDE + cc],     Bh[nt][0], Bl[nt][0]);
                    cvt3(Bs[(kk + lq + 4) * BS_STRIDE + cc], Bh[nt][1], Bl[nt][1]);
                } else {
                    Bh[nt][0] = __float_as_uint(Bs[(kk + lq) * BS_STRIDE + cc]);
                    Bh[nt][1] = __float_as_uint(Bs[(kk + lq + 4) * BS_STRIDE + cc]);
                }
            }
#pragma unroll
            for (int mt = 0; mt < 4; mt++)
#pragma unroll
                for (int nt = 0; nt < 8; nt++) {
                    MMA8(acc[mt][nt], Ah[mt], Bh[nt]);
                    if (SPLIT3) {
                        MMA8(acc[mt][nt], Al[mt], Bh[nt]);
                        MMA8(acc[mt][nt], Ah[mt], Bl[nt]);
                    }
                }
        }
        __syncthreads();
    }

#pragma unroll
    for (int mt = 0; mt < 4; mt++) {
        int row = m0 + wm + mt * 16 + lr;
#pragma unroll
        for (int nt = 0; nt < 8; nt++) {
            int col = n0 + wn + nt * 8 + lq * 2;
            if (SPLIT3) {
                *(float2*)(C + (size_t)row * N + col) =
                    make_float2(acc[mt][nt][0], acc[mt][nt][1]);
                *(float2*)(C + (size_t)(row + 8) * N + col) =
                    make_float2(acc[mt][nt][2], acc[mt][nt][3]);
            } else {
                *(float2*)(C + (size_t)row * N + col) =
                    make_float2(rtf32(acc[mt][nt][0]), rtf32(acc[mt][nt][1]));
                *(float2*)(C + (size_t)(row + 8) * N + col) =
                    make_float2(rtf32(acc[mt][nt][2]), rtf32(acc[mt][nt][3]));
            }
        }
    }
}

// ===========================================================================
// closed-form E8 argmin
// ===========================================================================
__global__ __launch_bounds__(256) void e8_argmin_fast() {
    int id = blockIdx.x * 256 + threadIdx.x;
    int t = id & (SEQ - 1), h = (id >> 11) & 15, b = id >> 15;
    size_t off = ((size_t)(b * SEQ + t)) * 128 + h * 8;
    float x[8];
#pragma unroll
    for (int j = 0; j < 8; j++) x[j] = g_coords[off + j] + g_coords2[off + j];

    int i1 = 0, i2 = -1;
    float m1 = fabsf(x[0]), m2 = -1.f;
#pragma unroll
    for (int j = 1; j < 8; j++) {
        float a = fabsf(x[j]);
        if (a > m1) { m2 = m1; i2 = i1; m1 = a; i1 = j; }
        else if (a > m2) { m2 = a; i2 = j; }
    }
    int a = min(i1, i2), bb = max(i1, i2);
    float dotp = m1 + m2;
    int p = a * 7 - (a * (a - 1)) / 2 + (bb - a - 1);
    int s = ((x[a] < 0.f) ? 2 : 0) | ((x[bb] < 0.f) ? 1 : 0);
    int idx_pair = p * 4 + s;

    float S = 0.f, mn = 3.4e38f;
    int mni = 0, mask = 0, cnt = 0;
#pragma unroll
    for (int j = 0; j < 8; j++) {
        float aa = fabsf(x[j]);
        S += aa;
        if (aa < mn) { mn = aa; mni = j; }
        if (x[j] < 0.f) { mask |= 1 << j; cnt++; }
    }
    if (cnt & 1) mask ^= (1 << mni);
    float doth = 0.5f * S - ((cnt & 1) ? mn : 0.f);

    g_idx[id] = (dotp >= doth) ? idx_pair : (112 + (mask >> 1));
}

// ===========================================================================
// attn_mid: FUSED rgemm + exp + running lp + partial PV + running P cumsum.
// ===========================================================================
#define AM_AS 0
#define AM_ES (64 * 68)
#define AM_K  (AM_ES + 64 * 68)
#define AM_V  (AM_K + 2 * 64 * 68)
#define AM_RS (AM_V + 2 * 64 * 72)
#define AM_RUN (AM_RS + 64)
#define AM_SMEM ((AM_RUN + 64) * 4)

__global__ __launch_bounds__(256) void attn_mid() {
    float* As = smf + AM_AS;
    float* Es = smf + AM_ES;
    float* rsum = smf + AM_RS;
    float* running = smf + AM_RUN;
    uint32_t sb = smem_u32(smf);

    int tid = threadIdx.x;
    int lane = tid & 31, w = tid >> 5;
    int lq = lane & 3, lr = lane >> 2;
    int wm = (w & 3) * 16, wt = (w >> 2) * 32;
    int m0 = blockIdx.x * 64, bh = blockIdx.y;
    int b = bh >> 4, h = bh & 15;

#pragma unroll
    for (int i = 0; i < 4; i++) {
        int idx = tid + i * 256;
        int r = idx >> 4, c4 = (idx & 15) * 4;
        int m = m0 + r;
        float4 a = (m < NROOT) ? *(const float4*)(g_RW + m * HDIM + c4)
                               : make_float4(0, 0, 0, 0);
        *(float4*)(As + r * 68 + c4) = a;
    }
    if (tid < 64) { running[tid] = 0.f; rsum[tid] = 0.f; }

    auto load_kv = [&](int j, int buf) {
        int t0 = j * 64;
#pragma unroll
        for (int i = 0; i < 4; i++) {
            int idx = tid + i * 256;
            int r = idx >> 4, c4 = (idx & 15) * 4;
            const float* kp = g_k + ((size_t)b * SEQ + t0 + r) * DMODEL + h * HDIM + c4;
            const float* vp = g_v + ((size_t)b * SEQ + t0 + r) * DMODEL + h * HDIM + c4;
            CP16(sb + (uint32_t)(AM_K + buf * 64 * 68 + r * 68 + c4) * 4, kp);
            CP16(sb + (uint32_t)(AM_V + buf * 64 * 72 + r * 72 + c4) * 4, vp);
        }
        CP_COMMIT();
    };
    load_kv(0, 0);

    float pacc[4][4];
#pragma unroll
    for (int nt = 0; nt < 4; nt++)
#pragma unroll
        for (int q = 0; q < 4; q++) pacc[nt][q] = 0.f;

    int mA = m0 + wm + lr, mB = mA + 8;

    for (int j = 0; j < NTILE; j++) {
        CP_WAIT(0);
        __syncthreads();   // all threads done with iteration j-1 (incl. PV reads)
        if (j < NTILE - 1) load_kv(j + 1, (j + 1) & 1);

        const float* Kb = smf + AM_K + (j & 1) * 64 * 68;
        const float* Vb = smf + AM_V + (j & 1) * 64 * 72;

        float sacc[4][4];
#pragma unroll
        for (int nt = 0; nt < 4; nt++)
#pragma unroll
            for (int q = 0; q < 4; q++) sacc[nt][q] = 0.f;
#pragma unroll
        for (int ks = 0; ks < 8; ks++) {
            int kk = ks * 8;
            uint32_t a[4];
            a[0] = __float_as_uint(As[(wm + lr) * 68 + kk + lq]);
            a[1] = __float_as_uint(As[(wm + lr + 8) * 68 + kk + lq]);
            a[2] = __float_as_uint(As[(wm + lr) * 68 + kk + lq + 4]);
            a[3] = __float_as_uint(As[(wm + lr + 8) * 68 + kk + lq + 4]);
#pragma unroll
            for (int nt = 0; nt < 4; nt++) {
                int cc = wt + nt * 8 + lr;
                uint32_t bb[2];
                bb[0] = __float_as_uint(Kb[cc * 68 + kk + lq]);
                bb[1] = __float_as_uint(Kb[cc * 68 + kk + lq + 4]);
                MMA8(sacc[nt], a, bb);
            }
        }

        float sA = 0.f, sB = 0.f;
#pragma unroll
        for (int nt = 0; nt < 4; nt++) {
            float e0 = rtf32(__expf(sacc[nt][0]));
            float e1 = rtf32(__expf(sacc[nt][1]));
            float e2 = rtf32(__expf(sacc[nt][2]));
            float e3 = rtf32(__expf(sacc[nt][3]));
            sA += e0 + e1; sB += e2 + e3;
            int col = wt + nt * 8 + lq * 2;
            Es[(wm + lr) * 68 + col] = e0;
            Es[(wm + lr) * 68 + col + 1] = e1;
            Es[(wm + lr + 8) * 68 + col] = e2;
            Es[(wm + lr + 8) * 68 + col + 1] = e3;
        }
        sA += __shfl_xor_sync(0xffffffffu, sA, 1);
        sA += __shfl_xor_sync(0xffffffffu, sA, 2);
        sB += __shfl_xor_sync(0xffffffffu, sB, 1);
        sB += __shfl_xor_sync(0xffffffffu, sB, 2);
        if (lq == 0) {
            atomicAdd(&rsum[wm + lr], sA);
            atomicAdd(&rsum[wm + lr + 8], sB);
        }
        __syncthreads();   // Es + rsum visible

#pragma unroll
        for (int ks = 0; ks < 8; ks++) {
            int kk = ks * 8;
            uint32_t a[4];
            a[0] = __float_as_uint(Es[(wm + lr) * 68 + kk + lq]);
            a[1] = __float_as_uint(Es[(wm + lr + 8) * 68 + kk + lq]);
            a[2] = __float_as_uint(Es[(wm + lr) * 68 + kk + lq + 4]);
            a[3] = __float_as_uint(Es[(wm + lr + 8) * 68 + kk + lq + 4]);
#pragma unroll
            for (int nt = 0; nt < 4; nt++) {
                int cc = wt + nt * 8 + lr;
                uint32_t bb[2];
                bb[0] = __float_as_uint(Vb[(kk + lq) * 72 + cc]);
                bb[1] = __float_as_uint(Vb[(kk + lq + 4) * 72 + cc]);
                MMA8(pacc[nt], a, bb);
            }
        }

        if (tid < 64) {
            int m = m0 + tid;
            float r = running[tid] + rsum[tid];
            running[tid] = r;
            rsum[tid] = 0.f;
            if (m < NROOT) g_lp[(bh * NROOT + m) * NTILE + j] = r;
        }
        float* base = g_P + (size_t)(bh * NTILE + j) * NROOT * 64;
#pragma unroll
        for (int nt = 0; nt < 4; nt++) {
            int d = wt + nt * 8 + lq * 2;
            if (mA < NROOT) *(float2*)(base + mA * 64 + d) = make_float2(pacc[nt][0], pacc[nt][1]);
            if (mB < NROOT) *(float2*)(base + mB * 64 + d) = make_float2(pacc[nt][2], pacc[nt][3]);
        }
    }
}

// ===========================================================================
// attn_diag: recompute diagonal S from gathered RW rows + diagonal K tile,
// exp + causal zero + rowsum, PV mma, add cumulative prefix.
// ===========================================================================
__global__ __launch_bounds__(256) void attn_diag() {
    __shared__ float RWs[64 * 68];
    __shared__ float Kd[64 * 68];
    __shared__ float Ps[64 * 68];
    __shared__ float Vs[64 * 72];
    __shared__ float rsum[64];
    __shared__ int sidx[64];
    int tid = threadIdx.x;
    int lane = tid & 31, w = tid >> 5;
    int lq = lane & 3, lr = lane >> 2;
    int wm = (w & 3) * 16, wt = (w >> 2) * 32;
    int mblk = blockIdx.x, bh = blockIdx.y;
    int b = bh >> 4, h = bh & 15;
    int m0 = mblk * 64;
    if (tid < 64) { sidx[tid] = g_idx[bh * SEQ + m0 + tid]; rsum[tid] = 0.f; }
    __syncthreads();

#pragma unroll
    for (int i = 0; i < 4; i++) {
        int idx = tid + i * 256;
        int r = idx >> 4, c4 = (idx & 15) * 4;
        *(float4*)(RWs + r * 68 + c4) = *(const float4*)(g_RW + sidx[r] * HDIM + c4);
        float4 kk = *(const float4*)(g_k + ((size_t)b * SEQ + m0 + r) * DMODEL + h * HDIM + c4);
        *(float4*)(Kd + r * 68 + c4) = kk;
        float4 vv = *(const float4*)(g_v + ((size_t)b * SEQ + m0 + r) * DMODEL + h * HDIM + c4);
        *(float4*)(Vs + r * 72 + c4) = vv;
    }
    __syncthreads();

    float sacc[4][4];
#pragma unroll
    for (int nt = 0; nt < 4; nt++)
#pragma unroll
        for (int q = 0; q < 4; q++) sacc[nt][q] = 0.f;
#pragma unroll
    for (int ks = 0; ks < 8; ks++) {
        int kk = ks * 8;
        uint32_t a[4];
        a[0] = __float_as_uint(RWs[(wm + lr) * 68 + kk + lq]);
        a[1] = __float_as_uint(RWs[(wm + lr + 8) * 68 + kk + lq]);
        a[2] = __float_as_uint(RWs[(wm + lr) * 68 + kk + lq + 4]);
        a[3] = __float_as_uint(RWs[(wm + lr + 8) * 68 + kk + lq + 4]);
#pragma unroll
        for (int nt = 0; nt < 4; nt++) {
            int cc = wt + nt * 8 + lr;
            uint32_t bb[2];
            bb[0] = __float_as_uint(Kd[cc * 68 + kk + lq]);
            bb[1] = __float_as_uint(Kd[cc * 68 + kk + lq + 4]);
            MMA8(sacc[nt], a, bb);
        }
    }

    {
        int qA = wm + lr, qB = qA + 8;
        float sA = 0.f, sB = 0.f;
#pragma unroll
        for (int nt = 0; nt < 4; nt++) {
            int col = wt + nt * 8 + lq * 2;
            float e0 = (col     <= qA) ? rtf32(__expf(sacc[nt][0])) : 0.f;
            float e1 = (col + 1 <= qA) ? rtf32(__expf(sacc[nt][1])) : 0.f;
            float e2 = (col     <= qB) ? rtf32(__expf(sacc[nt][2])) : 0.f;
            float e3 = (col + 1 <= qB) ? rtf32(__expf(sacc[nt][3])) : 0.f;
            sA += e0 + e1; sB += e2 + e3;
            Ps[qA * 68 + col] = e0;
            Ps[qA * 68 + col + 1] = e1;
            Ps[qB * 68 + col] = e2;
            Ps[qB * 68 + col + 1] = e3;
        }
        sA += __shfl_xor_sync(0xffffffffu, sA, 1);
        sA += __shfl_xor_sync(0xffffffffu, sA, 2);
        sB += __shfl_xor_sync(0xffffffffu, sB, 1);
        sB += __shfl_xor_sync(0xffffffffu, sB, 2);
        if (lq == 0) {
            atomicAdd(&rsum[qA], sA);
            atomicAdd(&rsum[qB], sB);
        }
    }
    __syncthreads();

    float acc[4][4];
#pragma unroll
    for (int nt = 0; nt < 4; nt++)
#pragma unroll
        for (int q = 0; q < 4; q++) acc[nt][q] = 0.f;
#pragma unroll
    for (int ks = 0; ks < 8; ks++) {
        int kk = ks * 8;
        uint32_t a[4];
        a[0] = __float_as_uint(Ps[(wm + lr) * 68 + kk + lq]);
        a[1] = __float_as_uint(Ps[(wm + lr + 8) * 68 + kk + lq]);
        a[2] = __float_as_uint(Ps[(wm + lr) * 68 + kk + lq + 4]);
        a[3] = __float_as_uint(Ps[(wm + lr + 8) * 68 + kk + lq + 4]);
#pragma unroll
        for (int nt = 0; nt < 4; nt++) {
            int cc = wt + nt * 8 + lr;
            uint32_t bb[2];
            bb[0] = __float_as_uint(Vs[(kk + lq) * 72 + cc]);
            bb[1] = __float_as_uint(Vs[(kk + lq + 4) * 72 + cc]);
            MMA8(acc[nt], a, bb);
        }
    }

    int rA = wm + lr, rB = rA + 8;
    int rootA = sidx[rA], rootB = sidx[rB];
    float lA = rsum[rA], lB = rsum[rB];
    const float* cpA = nullptr;
    const float* cpB = nullptr;
    if (mblk > 0) {
        lA += g_lp[(bh * NROOT + rootA) * NTILE + mblk - 1];
        lB += g_lp[(bh * NROOT + rootB) * NTILE + mblk - 1];
        cpA = g_P + ((size_t)(bh * NTILE + mblk - 1) * NROOT + rootA) * 64;
        cpB = g_P + ((size_t)(bh * NTILE + mblk - 1) * NROOT + rootB) * 64;
    }
    float invA = 1.0f / lA, invB = 1.0f / lB;
    float* oA = g_o + ((size_t)b * SEQ + m0 + rA) * DMODEL + h * HDIM;
    float* oB = g_o + ((size_t)b * SEQ + m0 + rB) * DMODEL + h * HDIM;
#pragma unroll
    for (int nt = 0; nt < 4; nt++) {
        int d = wt + nt * 8 + lq * 2;
        float pa0 = 0.f, pa1 = 0.f, pb0 = 0.f, pb1 = 0.f;
        if (mblk > 0) {
            float2 t0 = *(const float2*)(cpA + d); pa0 = t0.x; pa1 = t0.y;
            float2 t1 = *(const float2*)(cpB + d); pb0 = t1.x; pb1 = t1.y;
        }
        *(float2*)(oA + d) = make_float2(rtf32((acc[nt][0] + pa0) * invA),
                                         rtf32((acc[nt][1] + pa1) * invA));
        *(float2*)(oB + d) = make_float2(rtf32((acc[nt][2] + pb0) * invB),
                                         rtf32((acc[nt][3] + pb1) * invB));
    }
}

// ---------------------------------------------------------------------------
// Launch
// ---------------------------------------------------------------------------
extern "C" void kernel_launch(void* const* d_in, const int* in_sizes, int n_in,
                              void* d_out, int out_size) {
    const float* x     = (const float*)d_in[0];
    const float* Wq    = (const float*)d_in[1];
    const float* Wk    = (const float*)d_in[2];
    const float* Wv    = (const float*)d_in[3];
    const float* Wte8  = (const float*)d_in[4];
    const float* Wfe8  = (const float*)d_in[5];
    const float* Wout  = (const float*)d_in[6];
    float* out = (float*)d_out;

    float *k, *v, *o, *coords, *coords2, *wqe8, *xr, *wkr, *wvr, *wor;
    cudaGetSymbolAddress((void**)&k, g_k);
    cudaGetSymbolAddress((void**)&v, g_v);
    cudaGetSymbolAddress((void**)&o, g_o);
    cudaGetSymbolAddress((void**)&coords, g_coords);
    cudaGetSymbolAddress((void**)&coords2, g_coords2);
    cudaGetSymbolAddress((void**)&wqe8, g_Wqe8);
    cudaGetSymbolAddress((void**)&xr, g_xr);
    cudaGetSymbolAddress((void**)&wkr, g_wkr);
    cudaGetSymbolAddress((void**)&wvr, g_wvr);
    cudaGetSymbolAddress((void**)&wor, g_wor);

    cudaFuncSetAttribute(gemm_mma<true>,  cudaFuncAttributeMaxDynamicSharedMemorySize, GM_SMEM);
    cudaFuncSetAttribute(gemm_mma<false>, cudaFuncAttributeMaxDynamicSharedMemorySize, GM_SMEM);
    cudaFuncSetAttribute(attn_mid, cudaFuncAttributeMaxDynamicSharedMemorySize, AM_SMEM);

    static cudaStream_t s2 = nullptr;
    static cudaEvent_t evF = nullptr, evJ = nullptr;
    if (s2 == nullptr) {
        cudaStreamCreateWithFlags(&s2, cudaStreamNonBlocking);
        cudaEventCreateWithFlags(&evF, cudaEventDisableTiming);
        cudaEventCreateWithFlags(&evJ, cudaEventDisableTiming);
    }

    // fused prep
    prep<<<PREP_BLKS, 256>>>(x, Wq, Wk, Wv, Wout, Wte8, Wfe8);

    // fork: coords (split-K, high precision) + argmin on side stream
    cudaEventRecord(evF, 0);
    cudaStreamWaitEvent(s2, evF, 0);
    gemm_mma<true><<<dim3(1, 32, 2), 128, GM_SMEM, s2>>>(
        x, wqe8, coords, wqe8 + 512 * 128, coords2, 128, 512, DMODEL, 512);
    e8_argmin_fast<<<256, 256, 0, s2>>>();
    cudaEventRecord(evJ, s2);

    // main stream: K/V then fused mid-chain
    gemm_mma<false><<<dim3(8, 32, 2), 128, GM_SMEM>>>(
        xr, wkr, k, wvr, v, DMODEL, DMODEL, DMODEL, 0);

    attn_mid<<<dim3(4, NBH), 256, AM_SMEM>>>();

    // join: attn_diag needs g_idx
    cudaStreamWaitEvent(0, evJ, 0);
    attn_diag<<<dim3(32, NBH), 256>>>();

    // output projection
    gemm_mma<false><<<dim3(8, 32, 1), 128, GM_SMEM>>>(
        o, wor, out, wor, out, DMODEL, DMODEL, DMODEL, 0);
}

// round 17
// speedup vs baseline: 1.1157x; 1.0328x over previous
#include <cuda_runtime.h>
#include <cuda_bf16.h>
#include <math.h>
#include <stdint.h>

#define BATCH 2
#define SEQ   2048
#define DMODEL 1024
#define NHEAD 16
#define HDIM  64
#define MROWS (BATCH*SEQ)          // 4096
#define NBH   (BATCH*NHEAD)        // 32
#define NROOT 240
#define NTILE 32                   // key tiles of 64

// Scratch (device globals; no allocation allowed)
__device__ float g_k[MROWS*DMODEL];
__device__ float g_v[MROWS*DMODEL];
__device__ float g_o[MROWS*DMODEL];
__device__ float g_xr[MROWS*DMODEL];        // tf32-rounded x
__device__ float g_wkr[DMODEL*DMODEL];
__device__ float g_wvr[DMODEL*DMODEL];
__device__ float g_wor[DMODEL*DMODEL];
__device__ float g_P[NBH*NTILE*NROOT*64];   // CUMULATIVE per-tile PV partials (sparse)
__device__ float g_lp[NBH*NROOT*NTILE];     // CUMULATIVE per-tile E-row sums
__device__ float g_coords[MROWS*128];
__device__ float g_coords2[MROWS*128];
__device__ int   g_idx[NBH*SEQ];
__device__ uint32_t g_bmap[NBH*NTILE*8];    // which roots' P rows tile j+1 needs
__device__ float g_Wqe8[DMODEL*128];
__device__ float g_RW[NROOT*HDIM];

// ===========================================================================
// helpers
// ===========================================================================
__device__ __forceinline__ uint32_t smem_u32(const void* p) {
    uint32_t a;
    asm("{ .reg .u64 t; cvta.to.shared.u64 t, %1; cvt.u32.u64 %0, t; }"
        : "=r"(a) : "l"(p));
    return a;
}
#define CP16(dst, src) \
    asm volatile("cp.async.cg.shared.global [%0], [%1], 16;" :: "r"(dst), "l"(src) : "memory")
#define CP_COMMIT() asm volatile("cp.async.commit_group;" ::: "memory")
#define CP_WAIT(n)  asm volatile("cp.async.wait_group %0;" :: "n"(n) : "memory")

__device__ __forceinline__ void cvt3(float x, uint32_t& hi, uint32_t& lo) {
    asm("cvt.rna.tf32.f32 %0, %1;" : "=r"(hi) : "f"(x));
    float r = x - __uint_as_float(hi);
    asm("cvt.rna.tf32.f32 %0, %1;" : "=r"(lo) : "f"(r));
}
__device__ __forceinline__ uint32_t cvt1(float x) {
    uint32_t t;
    asm("cvt.rna.tf32.f32 %0, %1;" : "=r"(t) : "f"(x));
    return t;
}
__device__ __forceinline__ float rtf32(float x) { return __uint_as_float(cvt1(x)); }

#define MMA8(c, a, b) \
    asm volatile("mma.sync.aligned.m16n8k8.row.col.f32.tf32.tf32.f32 " \
        "{%0,%1,%2,%3}, {%4,%5,%6,%7}, {%8,%9}, {%0,%1,%2,%3};" \
        : "+f"((c)[0]), "+f"((c)[1]), "+f"((c)[2]), "+f"((c)[3]) \
        : "r"((a)[0]), "r"((a)[1]), "r"((a)[2]), "r"((a)[3]), \
          "r"((b)[0]), "r"((b)[1]))

// ===========================================================================
// prep_xw: round x + round Wk/Wv/Wout (main stream; feeds KV GEMM)
// ===========================================================================
#define PB_X (MROWS * DMODEL / 256)      // 16384
#define PB_W (DMODEL * DMODEL / 256)     // 4096
#define PXW_BLKS (PB_X + 3 * PB_W)

__global__ __launch_bounds__(256) void prep_xw(const float* __restrict__ x,
                                               const float* __restrict__ Wk,
                                               const float* __restrict__ Wv,
                                               const float* __restrict__ Wo) {
    int tid = threadIdx.x;
    int blk = blockIdx.x;
    if (blk < PB_X) {
        int i = blk * 256 + tid;
        g_xr[i] = rtf32(x[i]);
        return;
    }
    blk -= PB_X;
    int sel = blk / PB_W;
    int i = (blk % PB_W) * 256 + tid;
    const float* s = (sel == 0) ? Wk : (sel == 1) ? Wv : Wo;
    float* d = (sel == 0) ? g_wkr : (sel == 1) ? g_wvr : g_wor;
    d[i] = rtf32(s[i]);
}

// ===========================================================================
// prep_tab: Wqe8, RW tables, zero g_bmap (side stream; feeds coords/argmin)
// ===========================================================================
#define PB_Q 512
#define PB_T 8
#define PB_Z 32                          // zero g_bmap: 8192 words / 256
#define PTB_BLKS (PB_Q + PB_T + PB_Z)

__global__ __launch_bounds__(256) void prep_tab(const float* __restrict__ Wq,
                                                const float* __restrict__ Wt,
                                                const float* __restrict__ Wf) {
    int tid = threadIdx.x;
    int blk = blockIdx.x;
    if (blk < PB_Q) {
        int i = blk * 256 + tid;           // < 1024*128
        int in = i >> 7, c = i & 127, h = c >> 3, j = c & 7;
        float s = 0.f;
#pragma unroll
        for (int e = 0; e < 64; e++) s += Wq[(size_t)in * DMODEL + h * 64 + e] * Wt[e * 8 + j];
        g_Wqe8[i] = s;
        return;
    }
    blk -= PB_Q;
    if (blk < PB_T) {
        __shared__ float roots[NROOT * 8];
        for (int i = tid; i < NROOT * 8; i += 256) {
            int r = i >> 3, d = i & 7;
            float v;
            if (r < 112) {
                int p = r >> 2, s = r & 3;
                int a = 0, b = 1, cnt = 0; bool done = false;
                for (a = 0; a < 8 && !done; a++) {
                    for (b = a + 1; b < 8; b++) {
                        if (cnt == p) { done = true; break; }
                        cnt++;
                    }
                }
                a--;
                float si = (s & 2) ? -1.f : 1.f;
                float sj = (s & 1) ? -1.f : 1.f;
                v = (d == a) ? si : ((d == b) ? sj : 0.f);
            } else {
                int k = r - 112;
                int mask = (k << 1) | (__popc(k) & 1);
                v = ((mask >> d) & 1) ? -0.5f : 0.5f;
            }
            roots[i] = v;
        }
        __syncthreads();
        int base = blk * (NROOT * HDIM / PB_T);    // 1920 per block
        for (int t = tid; t < NROOT * HDIM / PB_T; t += 256) {
            int i = base + t;
            int r = i >> 6, d = i & 63;
            float s = 0.f;
#pragma unroll
            for (int j = 0; j < 8; j++) s += roots[r * 8 + j] * Wf[j * HDIM + d];
            g_RW[i] = rtf32(0.125f * s);
        }
        return;
    }
    blk -= PB_T;
    g_bmap[blk * 256 + tid] = 0u;
}

// ===========================================================================
// mma.sync tf32 GEMM. 128 threads / 4 warps, warp tile 64x64. BS_STRIDE=136.
// ===========================================================================
#define AS_STRIDE 36
#define BS_STRIDE 136
#define AS_F (128 * AS_STRIDE)
#define BS_F (32 * BS_STRIDE)
#define STG_F (AS_F + BS_F)
#define GM_SMEM (2 * STG_F * 4)

extern __shared__ float smf[];

template <bool SPLIT3>
__global__ __launch_bounds__(128, SPLIT3 ? 1 : 2)
void gemm_mma(const float* __restrict__ A,
              const float* __restrict__ B0, float* __restrict__ C0,
              const float* __restrict__ B1, float* __restrict__ C1,
              int N, int K, int lda, int koff) {
    const float* B = blockIdx.z ? B1 : B0;
    float* C = blockIdx.z ? C1 : C0;
    A += (size_t)blockIdx.z * koff;
    int tid = threadIdx.x;
    int lane = tid & 31, w = tid >> 5;
    int lq = lane & 3, lr = lane >> 2;
    int wm = (w & 1) * 64, wn = (w >> 1) * 64;
    int n0 = blockIdx.x * 128, m0 = blockIdx.y * 128;
    uint32_t sb = smem_u32(smf);

    float acc[4][8][4];
#pragma unroll
    for (int mt = 0; mt < 4; mt++)
#pragma unroll
        for (int nt = 0; nt < 8; nt++)
#pragma unroll
            for (int j = 0; j < 4; j++) acc[mt][nt][j] = 0.f;

    int ar[8], aq[8], bk[8], bn[8];
#pragma unroll
    for (int i = 0; i < 8; i++) {
        int idx = tid + i * 128;
        ar[i] = idx >> 3; aq[i] = idx & 7;
        bk[i] = idx >> 5; bn[i] = idx & 31;
    }

    auto issue_chunk = [&](int c) {
        int k0 = c * 32;
        uint32_t base = sb + (uint32_t)(c & 1) * (STG_F * 4);
#pragma unroll
        for (int i = 0; i < 8; i++)
            CP16(base + (uint32_t)(ar[i] * AS_STRIDE + aq[i] * 4) * 4,
                 A + (size_t)(m0 + ar[i]) * lda + k0 + aq[i] * 4);
#pragma unroll
        for (int i = 0; i < 8; i++)
            CP16(base + (uint32_t)(AS_F + bk[i] * BS_STRIDE + bn[i] * 4) * 4,
                 B + (size_t)(k0 + bk[i]) * N + n0 + bn[i] * 4);
        CP_COMMIT();
    };

    issue_chunk(0);
    int nchunk = K >> 5;

    for (int c = 0; c < nchunk; c++) {
        if (c < nchunk - 1) { issue_chunk(c + 1); CP_WAIT(1); }
        else                { CP_WAIT(0); }
        __syncthreads();

        const float* As = smf + (c & 1) * STG_F;
        const float* Bs = As + AS_F;

#pragma unroll
        for (int ks = 0; ks < 4; ks++) {
            int kk = ks * 8;
            uint32_t Ah[4][4], Al[4][4];
#pragma unroll
            for (int mt = 0; mt < 4; mt++) {
                int rb = wm + mt * 16 + lr;
                if (SPLIT3) {
                    cvt3(As[rb * AS_STRIDE + kk + lq],           Ah[mt][0], Al[mt][0]);
                    cvt3(As[(rb + 8) * AS_STRIDE + kk + lq],     Ah[mt][1], Al[mt][1]);
                    cvt3(As[rb * AS_STRIDE + kk + lq + 4],       Ah[mt][2], Al[mt][2]);
                    cvt3(As[(rb + 8) * AS_STRIDE + kk + lq + 4], Ah[mt][3], Al[mt][3]);
                } else {
                    Ah[mt][0] = __float_as_uint(As[rb * AS_STRIDE + kk + lq]);
                    Ah[mt][1] = __float_as_uint(As[(rb + 8) * AS_STRIDE + kk + lq]);
                    Ah[mt][2] = __float_as_uint(As[rb * AS_STRIDE + kk + lq + 4]);
                    Ah[mt][3] = __float_as_uint(As[(rb + 8) * AS_STRIDE + kk + lq + 4]);
                }
            }
            uint32_t Bh[8][2], Bl[8][2];
#pragma unroll
            for (int nt = 0; nt < 8; nt++) {
                int cc = wn + nt * 8 + lr;
                if (SPLIT3) {
                    cvt3(Bs[(kk + lq) * BS_STRIDE + cc],     Bh[nt][0], Bl[nt][0]);
                    cvt3(Bs[(kk + lq + 4) * BS_STRIDE + cc], Bh[nt][1], Bl[nt][1]);
                } else {
                    Bh[nt][0] = __float_as_uint(Bs[(kk + lq) * BS_STRIDE + cc]);
                    Bh[nt][1] = __float_as_uint(Bs[(kk + lq + 4) * BS_STRIDE + cc]);
                }
            }
#pragma unroll
            for (int mt = 0; mt < 4; mt++)
#pragma unroll
                for (int nt = 0; nt < 8; nt++) {
                    MMA8(acc[mt][nt], Ah[mt], Bh[nt]);
                    if (SPLIT3) {
                        MMA8(acc[mt][nt], Al[mt], Bh[nt]);
                        MMA8(acc[mt][nt], Ah[mt], Bl[nt]);
                    }
                }
        }
        __syncthreads();
    }

#pragma unroll
    for (int mt = 0; mt < 4; mt++) {
        int row = m0 + wm + mt * 16 + lr;
#pragma unroll
        for (int nt = 0; nt < 8; nt++) {
            int col = n0 + wn + nt * 8 + lq * 2;
            if (SPLIT3) {
                *(float2*)(C + (size_t)row * N + col) =
                    make_float2(acc[mt][nt][0], acc[mt][nt][1]);
                *(float2*)(C + (size_t)(row + 8) * N + col) =
                    make_float2(acc[mt][nt][2], acc[mt][nt][3]);
            } else {
                *(float2*)(C + (size_t)row * N + col) =
                    make_float2(rtf32(acc[mt][nt][0]), rtf32(acc[mt][nt][1]));
                *(float2*)(C + (size_t)(row + 8) * N + col) =
                    make_float2(rtf32(acc[mt][nt][2]), rtf32(acc[mt][nt][3]));
            }
        }
    }
}

// ===========================================================================
// closed-form E8 argmin + root-usage bitmap for sparse P stores
// ===========================================================================
__global__ __launch_bounds__(256) void e8_argmin_fast() {
    int id = blockIdx.x * 256 + threadIdx.x;
    int t = id & (SEQ - 1);
    int bh = id >> 11;                    // b*16 + h
    size_t off = ((size_t)((id >> 15) * SEQ + t)) * 128 + ((bh & 15) * 8);
    float x[8];
#pragma unroll
    for (int j = 0; j < 8; j++) x[j] = g_coords[off + j] + g_coords2[off + j];

    int i1 = 0, i2 = -1;
    float m1 = fabsf(x[0]), m2 = -1.f;
#pragma unroll
    for (int j = 1; j < 8; j++) {
        float a = fabsf(x[j]);
        if (a > m1) { m2 = m1; i2 = i1; m1 = a; i1 = j; }
        else if (a > m2) { m2 = a; i2 = j; }
    }
    int a = min(i1, i2), bb = max(i1, i2);
    float dotp = m1 + m2;
    int p = a * 7 - (a * (a - 1)) / 2 + (bb - a - 1);
    int s = ((x[a] < 0.f) ? 2 : 0) | ((x[bb] < 0.f) ? 1 : 0);
    int idx_pair = p * 4 + s;

    float S = 0.f, mn = 3.4e38f;
    int mni = 0, mask = 0, cnt = 0;
#pragma unroll
    for (int j = 0; j < 8; j++) {
        float aa = fabsf(x[j]);
        S += aa;
        if (aa < mn) { mn = aa; mni = j; }
        if (x[j] < 0.f) { mask |= 1 << j; cnt++; }
    }
    if (cnt & 1) mask ^= (1 << mni);
    float doth = 0.5f * S - ((cnt & 1) ? mn : 0.f);

    int best = (dotp >= doth) ? idx_pair : (112 + (mask >> 1));
    g_idx[id] = best;

    // queries in tile jt read P of tile jt-1
    int jt = t >> 6;
    if (jt > 0)
        atomicOr(&g_bmap[(bh * NTILE + jt - 1) * 8 + (best >> 5)], 1u << (best & 31));
}

// ===========================================================================
// attn_mid: FUSED rgemm + exp + running lp + partial PV + running P cumsum.
// P stores gated by g_bmap (only rows attn_diag will actually read).
// ===========================================================================
#define AM_AS 0
#define AM_ES (64 * 68)
#define AM_K  (AM_ES + 64 * 68)
#define AM_V  (AM_K + 2 * 64 * 68)
#define AM_RS (AM_V + 2 * 64 * 72)
#define AM_RUN (AM_RS + 64)
#define AM_BM (AM_RUN + 64)
#define AM_SMEM ((AM_BM + 8) * 4)

__global__ __launch_bounds__(256) void attn_mid() {
    float* As = smf + AM_AS;
    float* Es = smf + AM_ES;
    float* rsum = smf + AM_RS;
    float* running = smf + AM_RUN;
    uint32_t* bmap_s = (uint32_t*)(smf + AM_BM);
    uint32_t sb = smem_u32(smf);

    int tid = threadIdx.x;
    int lane = tid & 31, w = tid >> 5;
    int lq = lane & 3, lr = lane >> 2;
    int wm = (w & 3) * 16, wt = (w >> 2) * 32;
    int m0 = blockIdx.x * 64, bh = blockIdx.y;
    int b = bh >> 4, h = bh & 15;

#pragma unroll
    for (int i = 0; i < 4; i++) {
        int idx = tid + i * 256;
        int r = idx >> 4, c4 = (idx & 15) * 4;
        int m = m0 + r;
        float4 a = (m < NROOT) ? *(const float4*)(g_RW + m * HDIM + c4)
                               : make_float4(0, 0, 0, 0);
        *(float4*)(As + r * 68 + c4) = a;
    }
    if (tid < 64) { running[tid] = 0.f; rsum[tid] = 0.f; }

    auto load_kv = [&](int j, int buf) {
        int t0 = j * 64;
#pragma unroll
        for (int i = 0; i < 4; i++) {
            int idx = tid + i * 256;
            int r = idx >> 4, c4 = (idx & 15) * 4;
            const float* kp = g_k + ((size_t)b * SEQ + t0 + r) * DMODEL + h * HDIM + c4;
            const float* vp = g_v + ((size_t)b * SEQ + t0 + r) * DMODEL + h * HDIM + c4;
            CP16(sb + (uint32_t)(AM_K + buf * 64 * 68 + r * 68 + c4) * 4, kp);
            CP16(sb + (uint32_t)(AM_V + buf * 64 * 72 + r * 72 + c4) * 4, vp);
        }
        CP_COMMIT();
    };
    load_kv(0, 0);

    float pacc[4][4];
#pragma unroll
    for (int nt = 0; nt < 4; nt++)
#pragma unroll
        for (int q = 0; q < 4; q++) pacc[nt][q] = 0.f;

    int mA = m0 + wm + lr, mB = mA + 8;

    for (int j = 0; j < NTILE; j++) {
        CP_WAIT(0);
        __syncthreads();   // all threads done with iteration j-1 (incl. PV reads)
        if (j < NTILE - 1) load_kv(j + 1, (j + 1) & 1);
        if (tid < 8) bmap_s[tid] = g_bmap[(bh * NTILE + j) * 8 + tid];

        const float* Kb = smf + AM_K + (j & 1) * 64 * 68;
        const float* Vb = smf + AM_V + (j & 1) * 64 * 72;

        float sacc[4][4];
#pragma unroll
        for (int nt = 0; nt < 4; nt++)
#pragma unroll
            for (int q = 0; q < 4; q++) sacc[nt][q] = 0.f;
#pragma unroll
        for (int ks = 0; ks < 8; ks++) {
            int kk = ks * 8;
            uint32_t a[4];
            a[0] = __float_as_uint(As[(wm + lr) * 68 + kk + lq]);
            a[1] = __float_as_uint(As[(wm + lr + 8) * 68 + kk + lq]);
            a[2] = __float_as_uint(As[(wm + lr) * 68 + kk + lq + 4]);
            a[3] = __float_as_uint(As[(wm + lr + 8) * 68 + kk + lq + 4]);
#pragma unroll
            for (int nt = 0; nt < 4; nt++) {
                int cc = wt + nt * 8 + lr;
                uint32_t bb[2];
                bb[0] = __float_as_uint(Kb[cc * 68 + kk + lq]);
                bb[1] = __float_as_uint(Kb[cc * 68 + kk + lq + 4]);
                MMA8(sacc[nt], a, bb);
            }
        }

        float sA = 0.f, sB = 0.f;
#pragma unroll
        for (int nt = 0; nt < 4; nt++) {
            float e0 = rtf32(__expf(sacc[nt][0]));
            float e1 = rtf32(__expf(sacc[nt][1]));
            float e2 = rtf32(__expf(sacc[nt][2]));
            float e3 = rtf32(__expf(sacc[nt][3]));
            sA += e0 + e1; sB += e2 + e3;
            int col = wt + nt * 8 + lq * 2;
            Es[(wm + lr) * 68 + col] = e0;
            Es[(wm + lr) * 68 + col + 1] = e1;
            Es[(wm + lr + 8) * 68 + col] = e2;
            Es[(wm + lr + 8) * 68 + col + 1] = e3;
        }
        sA += __shfl_xor_sync(0xffffffffu, sA, 1);
        sA += __shfl_xor_sync(0xffffffffu, sA, 2);
        sB += __shfl_xor_sync(0xffffffffu, sB, 1);
        sB += __shfl_xor_sync(0xffffffffu, sB, 2);
        if (lq == 0) {
            atomicAdd(&rsum[wm + lr], sA);
            atomicAdd(&rsum[wm + lr + 8], sB);
        }
        __syncthreads();   // Es + rsum + bmap_s visible

#pragma unroll
        for (int ks = 0; ks < 8; ks++) {
            int kk = ks * 8;
            uint32_t a[4];
            a[0] = __float_as_uint(Es[(wm + lr) * 68 + kk + lq]);
            a[1] = __float_as_uint(Es[(wm + lr + 8) * 68 + kk + lq]);
            a[2] = __float_as_uint(Es[(wm + lr) * 68 + kk + lq + 4]);
            a[3] = __float_as_uint(Es[(wm + lr + 8) * 68 + kk + lq + 4]);
#pragma unroll
            for (int nt = 0; nt < 4; nt++) {
                int cc = wt + nt * 8 + lr;
                uint32_t bb[2];
                bb[0] = __float_as_uint(Vb[(kk + lq) * 72 + cc]);
                bb[1] = __float_as_uint(Vb[(kk + lq + 4) * 72 + cc]);
                MMA8(pacc[nt], a, bb);
            }
        }

        if (tid < 64) {
            int m = m0 + tid;
            float r = running[tid] + rsum[tid];
            running[tid] = r;
            rsum[tid] = 0.f;
            if (m < NROOT) g_lp[(bh * NROOT + m) * NTILE + j] = r;
        }
        bool stA = (mA < NROOT) && ((bmap_s[mA >> 5] >> (mA & 31)) & 1);
        bool stB = (mB < NROOT) && ((bmap_s[mB >> 5] >> (mB & 31)) & 1);
        if (stA | stB) {
            float* base = g_P + (size_t)(bh * NTILE + j) * NROOT * 64;
#pragma unroll
            for (int nt = 0; nt < 4; nt++) {
                int d = wt + nt * 8 + lq * 2;
                if (stA) *(float2*)(base + mA * 64 + d) = make_float2(pacc[nt][0], pacc[nt][1]);
                if (stB) *(float2*)(base + mB * 64 + d) = make_float2(pacc[nt][2], pacc[nt][3]);
            }
        }
    }
}

// ===========================================================================
// attn_diag: recompute diagonal S from gathered RW rows + diagonal K tile,
// exp + causal zero + rowsum, PV mma, add cumulative prefix.
// ===========================================================================
__global__ __launch_bounds__(256) void attn_diag() {
    __shared__ float RWs[64 * 68];
    __shared__ float Kd[64 * 68];
    __shared__ float Ps[64 * 68];
    __shared__ float Vs[64 * 72];
    __shared__ float rsum[64];
    __shared__ int sidx[64];
    int tid = threadIdx.x;
    int lane = tid & 31, w = tid >> 5;
    int lq = lane & 3, lr = lane >> 2;
    int wm = (w & 3) * 16, wt = (w >> 2) * 32;
    int mblk = blockIdx.x, bh = blockIdx.y;
    int b = bh >> 4, h = bh & 15;
    int m0 = mblk * 64;
    if (tid < 64) { sidx[tid] = g_idx[bh * SEQ + m0 + tid]; rsum[tid] = 0.f; }
    __syncthreads();

#pragma unroll
    for (int i = 0; i < 4; i++) {
        int idx = tid + i * 256;
        int r = idx >> 4, c4 = (idx & 15) * 4;
        *(float4*)(RWs + r * 68 + c4) = *(const float4*)(g_RW + sidx[r] * HDIM + c4);
        float4 kk = *(const float4*)(g_k + ((size_t)b * SEQ + m0 + r) * DMODEL + h * HDIM + c4);
        *(float4*)(Kd + r * 68 + c4) = kk;
        float4 vv = *(const float4*)(g_v + ((size_t)b * SEQ + m0 + r) * DMODEL + h * HDIM + c4);
        *(float4*)(Vs + r * 72 + c4) = vv;
    }
    __syncthreads();

    float sacc[4][4];
#pragma unroll
    for (int nt = 0; nt < 4; nt++)
#pragma unroll
        for (int q = 0; q < 4; q++) sacc[nt][q] = 0.f;
#pragma unroll
    for (int ks = 0; ks < 8; ks++) {
        int kk = ks * 8;
        uint32_t a[4];
        a[0] = __float_as_uint(RWs[(wm + lr) * 68 + kk + lq]);
        a[1] = __float_as_uint(RWs[(wm + lr + 8) * 68 + kk + lq]);
        a[2] = __float_as_uint(RWs[(wm + lr) * 68 + kk + lq + 4]);
        a[3] = __float_as_uint(RWs[(wm + lr + 8) * 68 + kk + lq + 4]);
#pragma unroll
        for (int nt = 0; nt < 4; nt++) {
            int cc = wt + nt * 8 + lr;
            uint32_t bb[2];
            bb[0] = __float_as_uint(Kd[cc * 68 + kk + lq]);
            bb[1] = __float_as_uint(Kd[cc * 68 + kk + lq + 4]);
            MMA8(sacc[nt], a, bb);
        }
    }

    {
        int qA = wm + lr, qB = qA + 8;
        float sA = 0.f, sB = 0.f;
#pragma unroll
        for (int nt = 0; nt < 4; nt++) {
            int col = wt + nt * 8 + lq * 2;
            float e0 = (col     <= qA) ? rtf32(__expf(sacc[nt][0])) : 0.f;
            float e1 = (col + 1 <= qA) ? rtf32(__expf(sacc[nt][1])) : 0.f;
            float e2 = (col     <= qB) ? rtf32(__expf(sacc[nt][2])) : 0.f;
            float e3 = (col + 1 <= qB) ? rtf32(__expf(sacc[nt][3])) : 0.f;
            sA += e0 + e1; sB += e2 + e3;
            Ps[qA * 68 + col] = e0;
            Ps[qA * 68 + col + 1] = e1;
            Ps[qB * 68 + col] = e2;
            Ps[qB * 68 + col + 1] = e3;
        }
        sA += __shfl_xor_sync(0xffffffffu, sA, 1);
        sA += __shfl_xor_sync(0xffffffffu, sA, 2);
        sB += __shfl_xor_sync(0xffffffffu, sB, 1);
        sB += __shfl_xor_sync(0xffffffffu, sB, 2);
        if (lq == 0) {
            atomicAdd(&rsum[qA], sA);
            atomicAdd(&rsum[qB], sB);
        }
    }
    __syncthreads();

    float acc[4][4];
#pragma unroll
    for (int nt = 0; nt < 4; nt++)
#pragma unroll
        for (int q = 0; q < 4; q++) acc[nt][q] = 0.f;
#pragma unroll
    for (int ks = 0; ks < 8; ks++) {
        int kk = ks * 8;
        uint32_t a[4];
        a[0] = __float_as_uint(Ps[(wm + lr) * 68 + kk + lq]);
        a[1] = __float_as_uint(Ps[(wm + lr + 8) * 68 + kk + lq]);
        a[2] = __float_as_uint(Ps[(wm + lr) * 68 + kk + lq + 4]);
        a[3] = __float_as_uint(Ps[(wm + lr + 8) * 68 + kk + lq + 4]);
#pragma unroll
        for (int nt = 0; nt < 4; nt++) {
            int cc = wt + nt * 8 + lr;
            uint32_t bb[2];
            bb[0] = __float_as_uint(Vs[(kk + lq) * 72 + cc]);
            bb[1] = __float_as_uint(Vs[(kk + lq + 4) * 72 + cc]);
            MMA8(acc[nt], a, bb);
        }
    }

    int rA = wm + lr, rB = rA + 8;
    int rootA = sidx[rA], rootB = sidx[rB];
    float lA = rsum[rA], lB = rsum[rB];
    const float* cpA = nullptr;
    const float* cpB = nullptr;
    if (mblk > 0) {
        lA += g_lp[(bh * NROOT + rootA) * NTILE + mblk - 1];
        lB += g_lp[(bh * NROOT + rootB) * NTILE + mblk - 1];
        cpA = g_P + ((size_t)(bh * NTILE + mblk - 1) * NROOT + rootA) * 64;
        cpB = g_P + ((size_t)(bh * NTILE + mblk - 1) * NROOT + rootB) * 64;
    }
    float invA = 1.0f / lA, invB = 1.0f / lB;
    float* oA = g_o + ((size_t)b * SEQ + m0 + rA) * DMODEL + h * HDIM;
    float* oB = g_o + ((size_t)b * SEQ + m0 + rB) * DMODEL + h * HDIM;
#pragma unroll
    for (int nt = 0; nt < 4; nt++) {
        int d = wt + nt * 8 + lq * 2;
        float pa0 = 0.f, pa1 = 0.f, pb0 = 0.f, pb1 = 0.f;
        if (mblk > 0) {
            float2 t0 = *(const float2*)(cpA + d); pa0 = t0.x; pa1 = t0.y;
            float2 t1 = *(const float2*)(cpB + d); pb0 = t1.x; pb1 = t1.y;
        }
        *(float2*)(oA + d) = make_float2(rtf32((acc[nt][0] + pa0) * invA),
                                         rtf32((acc[nt][1] + pa1) * invA));
        *(float2*)(oB + d) = make_float2(rtf32((acc[nt][2] + pb0) * invB),
                                         rtf32((acc[nt][3] + pb1) * invB));
    }
}

// ---------------------------------------------------------------------------
// Launch
// ---------------------------------------------------------------------------
extern "C" void kernel_launch(void* const* d_in, const int* in_sizes, int n_in,
                              void* d_out, int out_size) {
    const float* x     = (const float*)d_in[0];
    const float* Wq    = (const float*)d_in[1];
    const float* Wk    = (const float*)d_in[2];
    const float* Wv    = (const float*)d_in[3];
    const float* Wte8  = (const float*)d_in[4];
    const float* Wfe8  = (const float*)d_in[5];
    const float* Wout  = (const float*)d_in[6];
    float* out = (float*)d_out;

    float *k, *v, *o, *coords, *coords2, *wqe8, *xr, *wkr, *wvr, *wor;
    cudaGetSymbolAddress((void**)&k, g_k);
    cudaGetSymbolAddress((void**)&v, g_v);
    cudaGetSymbolAddress((void**)&o, g_o);
    cudaGetSymbolAddress((void**)&coords, g_coords);
    cudaGetSymbolAddress((void**)&coords2, g_coords2);
    cudaGetSymbolAddress((void**)&wqe8, g_Wqe8);
    cudaGetSymbolAddress((void**)&xr, g_xr);
    cudaGetSymbolAddress((void**)&wkr, g_wkr);
    cudaGetSymbolAddress((void**)&wvr, g_wvr);
    cudaGetSymbolAddress((void**)&wor, g_wor);

    cudaFuncSetAttribute(gemm_mma<true>,  cudaFuncAttributeMaxDynamicSharedMemorySize, GM_SMEM);
    cudaFuncSetAttribute(gemm_mma<false>, cudaFuncAttributeMaxDynamicSharedMemorySize, GM_SMEM);
    cudaFuncSetAttribute(attn_mid, cudaFuncAttributeMaxDynamicSharedMemorySize, AM_SMEM);

    static cudaStream_t s2 = nullptr;
    static cudaEvent_t evF = nullptr, evJ = nullptr;
    if (s2 == nullptr) {
        cudaStreamCreateWithFlags(&s2, cudaStreamNonBlocking);
        cudaEventCreateWithFlags(&evF, cudaEventDisableTiming);
        cudaEventCreateWithFlags(&evJ, cudaEventDisableTiming);
    }

    // fork at t=0: side stream builds tables (+bmap zero) -> coords -> argmin
    cudaEventRecord(evF, 0);
    cudaStreamWaitEvent(s2, evF, 0);
    prep_tab<<<PTB_BLKS, 256, 0, s2>>>(Wq, Wte8, Wfe8);
    gemm_mma<true><<<dim3(1, 32, 2), 128, GM_SMEM, s2>>>(
        x, wqe8, coords, wqe8 + 512 * 128, coords2, 128, 512, DMODEL, 512);
    e8_argmin_fast<<<256, 256, 0, s2>>>();
    cudaEventRecord(evJ, s2);

    // main stream: x/W rounding, K/V GEMM
    prep_xw<<<PXW_BLKS, 256>>>(x, Wk, Wv, Wout);
    gemm_mma<false><<<dim3(8, 32, 2), 128, GM_SMEM>>>(
        xr, wkr, k, wvr, v, DMODEL, DMODEL, DMODEL, 0);

    // attn_mid needs g_bmap + g_RW (side stream): join here
    cudaStreamWaitEvent(0, evJ, 0);
    attn_mid<<<dim3(4, NBH), 256, AM_SMEM>>>();
    attn_diag<<<dim3(32, NBH), 256>>>();

    // output projection
    gemm_mma<false><<<dim3(8, 32, 1), 128, GM_SMEM>>>(
        o, wor, out, wor, out, DMODEL, DMODEL, DMODEL, 0);
}